// round 3
// baseline (speedup 1.0000x reference)
#include <cuda_runtime.h>
#include <cuda_bf16.h>
#include <math.h>

// Problem constants (fixed by the reference)
#define NN   50000      // nodes
#define EE   1600000    // edges
#define FIN  256
#define HD   128        // hidden
#define CC   40         // classes
#define PP   128        // prototypes

// ---------------------------------------------------------------------------
// Scratch (static device globals; no allocation in kernel_launch)
// ---------------------------------------------------------------------------
__device__ __align__(16) float g_A[(size_t)NN * HD];     // GEMM output / hn
__device__ __align__(16) float g_B[(size_t)NN * HD];     // aggregation output
__device__ int   g_deg[NN];
__device__ float g_dinv[NN];
__device__ int   g_rowptr[NN + 1];
__device__ int   g_cursor[NN];
__device__ int   g_csrc[EE];
__device__ float g_cw[EE];
__device__ __align__(16) float g_anchors[PP * HD];
__device__ __align__(16) float g_hp[PP * HD];

// ---------------------------------------------------------------------------
// Graph preprocessing
// ---------------------------------------------------------------------------
__global__ void k_zero_deg() {
    int i = blockIdx.x * blockDim.x + threadIdx.x;
    if (i < NN) g_deg[i] = 0;
}

__global__ void k_deg(const int* __restrict__ ei) {
    int e = blockIdx.x * blockDim.x + threadIdx.x;
    if (e < EE) atomicAdd(&g_deg[ei[EE + e]], 1);   // dst row
}

__global__ void k_dinv() {
    int i = blockIdx.x * blockDim.x + threadIdx.x;
    if (i < NN) g_dinv[i] = rsqrtf((float)(g_deg[i] + 1));  // +1 self loop
}

// Single-block exclusive scan of g_deg -> g_rowptr / g_cursor
__global__ void k_scan() {
    __shared__ int sh[1024];
    __shared__ int s_carry;
    int t = threadIdx.x;
    if (t == 0) s_carry = 0;
    __syncthreads();
    for (int base = 0; base < NN; base += 1024) {
        int idx = base + t;
        int v = (idx < NN) ? g_deg[idx] : 0;
        sh[t] = v;
        __syncthreads();
        #pragma unroll
        for (int off = 1; off < 1024; off <<= 1) {
            int x = (t >= off) ? sh[t - off] : 0;
            __syncthreads();
            sh[t] += x;
            __syncthreads();
        }
        int carry = s_carry;
        if (idx < NN) {
            int excl = carry + sh[t] - v;
            g_rowptr[idx] = excl;
            g_cursor[idx] = excl;
        }
        __syncthreads();
        if (t == 1023) s_carry = carry + sh[1023];
        __syncthreads();
    }
    if (t == 0) g_rowptr[NN] = s_carry;
}

__global__ void k_fill(const int* __restrict__ ei) {
    int e = blockIdx.x * blockDim.x + threadIdx.x;
    if (e >= EE) return;
    int s = ei[e];
    int d = ei[EE + e];
    int pos = atomicAdd(&g_cursor[d], 1);
    g_csrc[pos] = s;
    g_cw[pos]   = g_dinv[s];
}

// ---------------------------------------------------------------------------
// fp32 SGEMM: C[M x 128] = op(A)[M x K] * B, B either [K x 128] or [128 x K]^T
// EPI: 0 = none, 1 = x_rel epilogue (v+1)*0.5
// ---------------------------------------------------------------------------
template<bool RELU_A, bool B_TRANS, int EPI>
__global__ __launch_bounds__(256, 2)
void sgemm_n128(const float* __restrict__ A, const float* __restrict__ B,
                float* __restrict__ Cmat, int M, int K)
{
    const int BM = 128, BK = 16;
    __shared__ float As[BK][BM + 4];
    __shared__ float Bs[BK][BM + 4];

    int tid = threadIdx.x;
    int tx = tid & 15;        // col group (8 cols)
    int ty = tid >> 4;        // row group (8 rows)
    int row0 = blockIdx.x * BM;

    float acc[8][8];
    #pragma unroll
    for (int i = 0; i < 8; i++)
        #pragma unroll
        for (int j = 0; j < 8; j++) acc[i][j] = 0.f;

    for (int k0 = 0; k0 < K; k0 += BK) {
        // Load A tile: 128 x 16 = 512 float4
        #pragma unroll
        for (int l = 0; l < 2; l++) {
            int f = tid + l * 256;
            int r  = f >> 2;
            int k4 = (f & 3) * 4;
            int grow = row0 + r;
            float4 v = make_float4(0.f, 0.f, 0.f, 0.f);
            if (grow < M) v = *(const float4*)(A + (size_t)grow * K + k0 + k4);
            if (RELU_A) {
                v.x = fmaxf(v.x, 0.f); v.y = fmaxf(v.y, 0.f);
                v.z = fmaxf(v.z, 0.f); v.w = fmaxf(v.w, 0.f);
            }
            As[k4 + 0][r] = v.x; As[k4 + 1][r] = v.y;
            As[k4 + 2][r] = v.z; As[k4 + 3][r] = v.w;
        }
        // Load B tile
        if (!B_TRANS) {
            #pragma unroll
            for (int l = 0; l < 2; l++) {
                int f = tid + l * 256;
                int kr = f >> 5;
                int n4 = (f & 31) * 4;
                float4 v = *(const float4*)(B + (size_t)(k0 + kr) * 128 + n4);
                Bs[kr][n4 + 0] = v.x; Bs[kr][n4 + 1] = v.y;
                Bs[kr][n4 + 2] = v.z; Bs[kr][n4 + 3] = v.w;
            }
        } else {
            #pragma unroll
            for (int l = 0; l < 2; l++) {
                int f = tid + l * 256;
                int n  = f >> 2;
                int k4 = (f & 3) * 4;
                float4 v = *(const float4*)(B + (size_t)n * K + k0 + k4);
                Bs[k4 + 0][n] = v.x; Bs[k4 + 1][n] = v.y;
                Bs[k4 + 2][n] = v.z; Bs[k4 + 3][n] = v.w;
            }
        }
        __syncthreads();

        #pragma unroll
        for (int k = 0; k < BK; k++) {
            float ar[8], br[8];
            *(float4*)&ar[0] = *(const float4*)&As[k][ty * 8];
            *(float4*)&ar[4] = *(const float4*)&As[k][ty * 8 + 4];
            *(float4*)&br[0] = *(const float4*)&Bs[k][tx * 8];
            *(float4*)&br[4] = *(const float4*)&Bs[k][tx * 8 + 4];
            #pragma unroll
            for (int i = 0; i < 8; i++)
                #pragma unroll
                for (int j = 0; j < 8; j++)
                    acc[i][j] += ar[i] * br[j];
        }
        __syncthreads();
    }

    #pragma unroll
    for (int i = 0; i < 8; i++) {
        int r = row0 + ty * 8 + i;
        if (r >= M) continue;
        #pragma unroll
        for (int j = 0; j < 8; j += 4) {
            float4 v = make_float4(acc[i][j], acc[i][j + 1], acc[i][j + 2], acc[i][j + 3]);
            if (EPI == 1) {
                v.x = (v.x + 1.f) * 0.5f; v.y = (v.y + 1.f) * 0.5f;
                v.z = (v.z + 1.f) * 0.5f; v.w = (v.w + 1.f) * 0.5f;
            }
            *(float4*)(Cmat + (size_t)r * 128 + tx * 8 + j) = v;
        }
    }
}

// ---------------------------------------------------------------------------
// CSR aggregation: g[i,:] = sum_{e: dst=i} dinv[src]*dinv[i]*h[src,:]
//                           + dinv[i]^2 * h[i,:] + bias
// warp per node, float4 per lane
// ---------------------------------------------------------------------------
__global__ void k_agg(const float* __restrict__ h, const float* __restrict__ bias,
                      float* __restrict__ g)
{
    int warp = threadIdx.x >> 5, lane = threadIdx.x & 31;
    int node = blockIdx.x * 8 + warp;
    if (node >= NN) return;

    float di = g_dinv[node];
    float4 b  = *(const float4*)(bias + lane * 4);
    float4 hv = *(const float4*)(h + (size_t)node * 128 + lane * 4);
    float w0 = di * di;
    float4 acc = make_float4(b.x + w0 * hv.x, b.y + w0 * hv.y,
                             b.z + w0 * hv.z, b.w + w0 * hv.w);

    int beg = g_rowptr[node], end = g_rowptr[node + 1];
    #pragma unroll 4
    for (int e = beg; e < end; e++) {
        int   s = g_csrc[e];
        float w = g_cw[e] * di;
        float4 x = *(const float4*)(h + (size_t)s * 128 + lane * 4);
        acc.x += w * x.x; acc.y += w * x.y;
        acc.z += w * x.z; acc.w += w * x.w;
    }
    *(float4*)(g + (size_t)node * 128 + lane * 4) = acc;
}

// ---------------------------------------------------------------------------
// Row L2 normalize: hn = h / ||h||
// ---------------------------------------------------------------------------
__global__ void k_rownorm(const float* __restrict__ h, float* __restrict__ hn) {
    int warp = threadIdx.x >> 5, lane = threadIdx.x & 31;
    int node = blockIdx.x * 8 + warp;
    if (node >= NN) return;
    float4 v = *(const float4*)(h + (size_t)node * 128 + lane * 4);
    float s = v.x * v.x + v.y * v.y + v.z * v.z + v.w * v.w;
    #pragma unroll
    for (int off = 16; off; off >>= 1) s += __shfl_xor_sync(~0u, s, off);
    float inv = 1.0f / sqrtf(s);
    v.x *= inv; v.y *= inv; v.z *= inv; v.w *= inv;
    *(float4*)(hn + (size_t)node * 128 + lane * 4) = v;
}

__global__ void k_anchors(const float* __restrict__ hn, const int* __restrict__ prot) {
    int p = blockIdx.x, t = threadIdx.x;
    g_anchors[p * HD + t] = hn[(size_t)prot[p] * HD + t];
}

// hp = relu(anchors @ lw1 + lb1)
__global__ void k_proto_hp(const float* __restrict__ lw1, const float* __restrict__ lb1) {
    __shared__ float a[HD];
    int p = blockIdx.x, j = threadIdx.x;
    a[j] = g_anchors[p * HD + j];
    __syncthreads();
    float acc = lb1[j];
    #pragma unroll 8
    for (int k = 0; k < HD; k++) acc += a[k] * lw1[k * HD + j];
    g_hp[p * HD + j] = fmaxf(acc, 0.f);
}

// out_proto = log_softmax(hp @ lw2 + lb2)
__global__ void k_proto_out(const float* __restrict__ lw2, const float* __restrict__ lb2,
                            float* __restrict__ op)
{
    __shared__ float h[HD];
    __shared__ float lg[CC];
    __shared__ float red[2];
    int p = blockIdx.x, t = threadIdx.x;   // 64 threads
    h[t] = g_hp[p * HD + t];
    h[t + 64] = g_hp[p * HD + 64 + t];
    __syncthreads();
    if (t < CC) {
        float acc = lb2[t];
        #pragma unroll 8
        for (int j = 0; j < HD; j++) acc += h[j] * lw2[j * CC + t];
        lg[t] = acc;
    }
    __syncthreads();
    if (t == 0) {
        float m = -1e30f;
        for (int c = 0; c < CC; c++) m = fmaxf(m, lg[c]);
        float s = 0.f;
        for (int c = 0; c < CC; c++) s += expf(lg[c] - m);
        red[0] = m; red[1] = logf(s);
    }
    __syncthreads();
    if (t < CC) op[p * CC + t] = lg[t] - red[0] - red[1];
}

// out = log_softmax(x_rel @ out_proto), warp per node
__global__ void k_out(const float* __restrict__ xrel, const float* __restrict__ proto,
                      float* __restrict__ out)
{
    __shared__ float sp[PP * CC];   // 5120 floats
    __shared__ float srow[8][PP];
    int tid = threadIdx.x;
    for (int i = tid; i < PP * CC; i += 256) sp[i] = proto[i];
    int warp = tid >> 5, lane = tid & 31;
    int node = blockIdx.x * 8 + warp;
    if (node < NN) {
        float4 v = *(const float4*)(xrel + (size_t)node * PP + lane * 4);
        *(float4*)&srow[warp][lane * 4] = v;
    }
    __syncthreads();
    if (node >= NN) return;

    const float* r = srow[warp];
    int c2 = 32 + (lane & 7);
    float a0 = 0.f, a1 = 0.f;
    #pragma unroll 8
    for (int p = 0; p < PP; p++) {
        float x = r[p];
        a0 += x * sp[p * CC + lane];
        a1 += x * sp[p * CC + c2];
    }
    float m = a0;
    if (lane < 8) m = fmaxf(m, a1);
    #pragma unroll
    for (int off = 16; off; off >>= 1) m = fmaxf(m, __shfl_xor_sync(~0u, m, off));
    float se = expf(a0 - m) + ((lane < 8) ? expf(a1 - m) : 0.f);
    #pragma unroll
    for (int off = 16; off; off >>= 1) se += __shfl_xor_sync(~0u, se, off);
    float lse = m + logf(se);
    out[(size_t)node * CC + lane] = a0 - lse;
    if (lane < 8) out[(size_t)node * CC + 32 + lane] = a1 - lse;
}

// ---------------------------------------------------------------------------
// launch
// ---------------------------------------------------------------------------
extern "C" void kernel_launch(void* const* d_in, const int* in_sizes, int n_in,
                              void* d_out, int out_size)
{
    const float* x    = (const float*)d_in[0];
    const int*   ei   = (const int*)  d_in[1];
    const int*   prot = (const int*)  d_in[2];
    const float* W0   = (const float*)d_in[3];
    const float* b0   = (const float*)d_in[4];
    const float* Wh   = (const float*)d_in[5];
    const float* bh   = (const float*)d_in[6];
    const float* lw1  = (const float*)d_in[7];
    const float* lb1  = (const float*)d_in[8];
    const float* lw2  = (const float*)d_in[9];
    const float* lb2  = (const float*)d_in[10];

    float* out   = (float*)d_out;                      // [N, C]
    float* xrel  = out + (size_t)NN * CC;              // [N, P]
    float* oprot = xrel + (size_t)NN * PP;             // [P, C]

    // resolve device-global addresses for kernels that take pointers
    float *pA, *pB, *pAnch;
    cudaGetSymbolAddress((void**)&pA, g_A);
    cudaGetSymbolAddress((void**)&pB, g_B);
    cudaGetSymbolAddress((void**)&pAnch, g_anchors);

    const int TB = 256;
    dim3 gN((NN + TB - 1) / TB);
    dim3 gE((EE + TB - 1) / TB);
    dim3 gGemm((NN + 127) / 128);
    dim3 gWarp8((NN + 7) / 8);

    // --- graph preprocessing (rebuilt every call; deterministic work) ---
    k_zero_deg<<<gN, TB>>>();
    k_deg<<<gE, TB>>>(ei);
    k_dinv<<<gN, TB>>>();
    k_scan<<<1, 1024>>>();
    k_fill<<<gE, TB>>>(ei);

    // --- layer 0: h = x @ W0 ; aggregate ---
    sgemm_n128<false, false, 0><<<gGemm, 256>>>(x, W0, pA, NN, FIN);
    k_agg<<<gWarp8, 256>>>(pA, b0, pB);

    // --- layer 1: h = relu(g) @ Wh[0] ; aggregate ---
    sgemm_n128<true, false, 0><<<gGemm, 256>>>(pB, Wh, pA, NN, HD);
    k_agg<<<gWarp8, 256>>>(pA, bh, pB);

    // --- layer 2: h = relu(g) @ Wh[1] ; aggregate ---
    sgemm_n128<true, false, 0><<<gGemm, 256>>>(pB, Wh + HD * HD, pA, NN, HD);
    k_agg<<<gWarp8, 256>>>(pA, bh + HD, pB);

    // --- L2 normalize rows: hn in g_A ---
    k_rownorm<<<gWarp8, 256>>>(pB, pA);

    // --- anchors, proto head ---
    k_anchors<<<PP, HD>>>(pA, prot);
    k_proto_hp<<<PP, HD>>>(lw1, lb1);
    k_proto_out<<<PP, 64>>>(lw2, lb2, oprot);

    // --- x_rel = (hn @ anchors^T + 1) * 0.5 ---
    sgemm_n128<false, true, 1><<<gGemm, 256>>>(pA, pAnch, xrel, NN, HD);

    // --- out = log_softmax(x_rel @ out_proto) ---
    k_out<<<gWarp8, 256>>>(xrel, oprot, out);
}

// round 4
// speedup vs baseline: 1.2340x; 1.2340x over previous
#include <cuda_runtime.h>
#include <cuda_bf16.h>
#include <math.h>

// Problem constants (fixed by the reference)
#define NN   50000      // nodes
#define EE   1600000    // edges
#define FIN  256
#define HD   128        // hidden
#define CC   40         // classes
#define PP   128        // prototypes

// ---------------------------------------------------------------------------
// Scratch (static device globals; no allocation in kernel_launch)
// ---------------------------------------------------------------------------
__device__ __align__(16) float g_A[(size_t)NN * HD];     // GEMM output / hn
__device__ __align__(16) float g_B[(size_t)NN * HD];     // aggregation output
__device__ int   g_deg[NN];
__device__ float g_dinv[NN];
__device__ int   g_rowptr[NN];        // segment begin (unordered CSR)
__device__ int   g_cursor[NN];        // fill cursor; == segment end after k_fill
__device__ int   g_total;
__device__ int   g_csrc[EE];
__device__ float g_cw[EE];
__device__ __align__(16) float g_anchors[PP * HD];
__device__ __align__(16) float g_hp[PP * HD];

// ---------------------------------------------------------------------------
// packed f32x2 helpers (sm_103a)
// ---------------------------------------------------------------------------
__device__ __forceinline__ unsigned long long ffma2(unsigned long long a,
                                                    unsigned long long b,
                                                    unsigned long long c) {
    unsigned long long d;
    asm("fma.rn.f32x2 %0, %1, %2, %3;" : "=l"(d) : "l"(a), "l"(b), "l"(c));
    return d;
}
__device__ __forceinline__ unsigned long long dup2(float x) {
    unsigned long long d;
    asm("mov.b64 %0, {%1, %1};" : "=l"(d) : "f"(x));
    return d;
}
__device__ __forceinline__ float2 unpack2(unsigned long long v) {
    float lo, hi;
    asm("mov.b64 {%0, %1}, %2;" : "=f"(lo), "=f"(hi) : "l"(v));
    return make_float2(lo, hi);
}

// ---------------------------------------------------------------------------
// Graph preprocessing
// ---------------------------------------------------------------------------
__global__ void k_zero_deg() {
    int i = blockIdx.x * blockDim.x + threadIdx.x;
    if (i < NN) g_deg[i] = 0;
    if (i == 0) g_total = 0;
}

__global__ void k_deg(const int* __restrict__ ei) {
    int e = blockIdx.x * blockDim.x + threadIdx.x;
    if (e < EE) atomicAdd(&g_deg[ei[EE + e]], 1);   // dst row
}

__global__ void k_dinv() {
    int i = blockIdx.x * blockDim.x + threadIdx.x;
    if (i < NN) g_dinv[i] = rsqrtf((float)(g_deg[i] + 1));  // +1 self loop
}

// Unordered CSR segment allocation: beg = atomicAdd(total, deg).
// Segments are contiguous per node; node order of segments is irrelevant.
__global__ void k_rowbeg() {
    int i = blockIdx.x * blockDim.x + threadIdx.x;
    if (i < NN) {
        int d = g_deg[i];
        int beg = atomicAdd(&g_total, d);
        g_rowptr[i] = beg;
        g_cursor[i] = beg;
    }
}

__global__ void k_fill(const int* __restrict__ ei) {
    int e = blockIdx.x * blockDim.x + threadIdx.x;
    if (e >= EE) return;
    int s = ei[e];
    int d = ei[EE + e];
    int pos = atomicAdd(&g_cursor[d], 1);
    g_csrc[pos] = s;
    g_cw[pos]   = g_dinv[s];
}

// ---------------------------------------------------------------------------
// fp32 SGEMM via packed f32x2 FMA:
// C[M x 128] = op(A)[M x K] * B, B either [K x 128] or [128 x K]^T
// EPI: 0 = none, 1 = x_rel epilogue (v+1)*0.5
// ---------------------------------------------------------------------------
template<bool RELU_A, bool B_TRANS, int EPI>
__global__ __launch_bounds__(256, 2)
void sgemm_n128(const float* __restrict__ A, const float* __restrict__ B,
                float* __restrict__ Cmat, int M, int K)
{
    const int BM = 128, BK = 16;
    __shared__ __align__(16) float As[BK][BM + 4];
    __shared__ __align__(16) float Bs[BK][BM + 4];

    int tid = threadIdx.x;
    int tx = tid & 15;        // col group (8 cols)
    int ty = tid >> 4;        // row group (8 rows)
    int row0 = blockIdx.x * BM;

    // acc2[i][jp] holds C cols (2jp, 2jp+1) for row i, packed f32x2
    unsigned long long acc2[8][4];
    #pragma unroll
    for (int i = 0; i < 8; i++)
        #pragma unroll
        for (int jp = 0; jp < 4; jp++) acc2[i][jp] = 0ull;

    for (int k0 = 0; k0 < K; k0 += BK) {
        // Load A tile: 128 x 16 = 512 float4
        #pragma unroll
        for (int l = 0; l < 2; l++) {
            int f = tid + l * 256;
            int r  = f >> 2;
            int k4 = (f & 3) * 4;
            int grow = row0 + r;
            float4 v = make_float4(0.f, 0.f, 0.f, 0.f);
            if (grow < M) v = *(const float4*)(A + (size_t)grow * K + k0 + k4);
            if (RELU_A) {
                v.x = fmaxf(v.x, 0.f); v.y = fmaxf(v.y, 0.f);
                v.z = fmaxf(v.z, 0.f); v.w = fmaxf(v.w, 0.f);
            }
            As[k4 + 0][r] = v.x; As[k4 + 1][r] = v.y;
            As[k4 + 2][r] = v.z; As[k4 + 3][r] = v.w;
        }
        // Load B tile
        if (!B_TRANS) {
            #pragma unroll
            for (int l = 0; l < 2; l++) {
                int f = tid + l * 256;
                int kr = f >> 5;
                int n4 = (f & 31) * 4;
                float4 v = *(const float4*)(B + (size_t)(k0 + kr) * 128 + n4);
                Bs[kr][n4 + 0] = v.x; Bs[kr][n4 + 1] = v.y;
                Bs[kr][n4 + 2] = v.z; Bs[kr][n4 + 3] = v.w;
            }
        } else {
            #pragma unroll
            for (int l = 0; l < 2; l++) {
                int f = tid + l * 256;
                int n  = f >> 2;
                int k4 = (f & 3) * 4;
                float4 v = *(const float4*)(B + (size_t)n * K + k0 + k4);
                Bs[k4 + 0][n] = v.x; Bs[k4 + 1][n] = v.y;
                Bs[k4 + 2][n] = v.z; Bs[k4 + 3][n] = v.w;
            }
        }
        __syncthreads();

        #pragma unroll
        for (int k = 0; k < BK; k++) {
            float ar[8];
            *(float4*)&ar[0] = *(const float4*)&As[k][ty * 8];
            *(float4*)&ar[4] = *(const float4*)&As[k][ty * 8 + 4];
            // adjacent B cols come out of LDS.128 as aligned 64-bit pairs
            ulonglong2 b01 = *(const ulonglong2*)&Bs[k][tx * 8];
            ulonglong2 b23 = *(const ulonglong2*)&Bs[k][tx * 8 + 4];
            unsigned long long brp[4] = { b01.x, b01.y, b23.x, b23.y };
            #pragma unroll
            for (int i = 0; i < 8; i++) {
                unsigned long long ad = dup2(ar[i]);
                #pragma unroll
                for (int jp = 0; jp < 4; jp++)
                    acc2[i][jp] = ffma2(ad, brp[jp], acc2[i][jp]);
            }
        }
        __syncthreads();
    }

    #pragma unroll
    for (int i = 0; i < 8; i++) {
        int r = row0 + ty * 8 + i;
        if (r >= M) continue;
        #pragma unroll
        for (int jp = 0; jp < 4; jp += 2) {
            float2 c0 = unpack2(acc2[i][jp]);
            float2 c1 = unpack2(acc2[i][jp + 1]);
            float4 v = make_float4(c0.x, c0.y, c1.x, c1.y);
            if (EPI == 1) {
                v.x = (v.x + 1.f) * 0.5f; v.y = (v.y + 1.f) * 0.5f;
                v.z = (v.z + 1.f) * 0.5f; v.w = (v.w + 1.f) * 0.5f;
            }
            *(float4*)(Cmat + (size_t)r * 128 + tx * 8 + jp * 2) = v;
        }
    }
}

// ---------------------------------------------------------------------------
// CSR aggregation: g[i,:] = sum_{e: dst=i} dinv[src]*dinv[i]*h[src,:]
//                           + dinv[i]^2 * h[i,:] + bias
// warp per node, float4 per lane. end = g_cursor[node] (post-fill).
// ---------------------------------------------------------------------------
__global__ void k_agg(const float* __restrict__ h, const float* __restrict__ bias,
                      float* __restrict__ g)
{
    int warp = threadIdx.x >> 5, lane = threadIdx.x & 31;
    int node = blockIdx.x * 8 + warp;
    if (node >= NN) return;

    float di = g_dinv[node];
    float4 b  = *(const float4*)(bias + lane * 4);
    float4 hv = *(const float4*)(h + (size_t)node * 128 + lane * 4);
    float w0 = di * di;
    float4 acc = make_float4(b.x + w0 * hv.x, b.y + w0 * hv.y,
                             b.z + w0 * hv.z, b.w + w0 * hv.w);

    int beg = g_rowptr[node], end = g_cursor[node];
    #pragma unroll 4
    for (int e = beg; e < end; e++) {
        int   s = g_csrc[e];
        float w = g_cw[e] * di;
        float4 x = *(const float4*)(h + (size_t)s * 128 + lane * 4);
        acc.x += w * x.x; acc.y += w * x.y;
        acc.z += w * x.z; acc.w += w * x.w;
    }
    *(float4*)(g + (size_t)node * 128 + lane * 4) = acc;
}

// ---------------------------------------------------------------------------
// Row L2 normalize: hn = h / ||h||
// ---------------------------------------------------------------------------
__global__ void k_rownorm(const float* __restrict__ h, float* __restrict__ hn) {
    int warp = threadIdx.x >> 5, lane = threadIdx.x & 31;
    int node = blockIdx.x * 8 + warp;
    if (node >= NN) return;
    float4 v = *(const float4*)(h + (size_t)node * 128 + lane * 4);
    float s = v.x * v.x + v.y * v.y + v.z * v.z + v.w * v.w;
    #pragma unroll
    for (int off = 16; off; off >>= 1) s += __shfl_xor_sync(~0u, s, off);
    float inv = 1.0f / sqrtf(s);
    v.x *= inv; v.y *= inv; v.z *= inv; v.w *= inv;
    *(float4*)(hn + (size_t)node * 128 + lane * 4) = v;
}

__global__ void k_anchors(const float* __restrict__ hn, const int* __restrict__ prot) {
    int p = blockIdx.x, t = threadIdx.x;
    g_anchors[p * HD + t] = hn[(size_t)prot[p] * HD + t];
}

// hp = relu(anchors @ lw1 + lb1)
__global__ void k_proto_hp(const float* __restrict__ lw1, const float* __restrict__ lb1) {
    __shared__ float a[HD];
    int p = blockIdx.x, j = threadIdx.x;
    a[j] = g_anchors[p * HD + j];
    __syncthreads();
    float acc = lb1[j];
    #pragma unroll 8
    for (int k = 0; k < HD; k++) acc += a[k] * lw1[k * HD + j];
    g_hp[p * HD + j] = fmaxf(acc, 0.f);
}

// out_proto = log_softmax(hp @ lw2 + lb2)
__global__ void k_proto_out(const float* __restrict__ lw2, const float* __restrict__ lb2,
                            float* __restrict__ op)
{
    __shared__ float h[HD];
    __shared__ float lg[CC];
    __shared__ float red[2];
    int p = blockIdx.x, t = threadIdx.x;   // 64 threads
    h[t] = g_hp[p * HD + t];
    h[t + 64] = g_hp[p * HD + 64 + t];
    __syncthreads();
    if (t < CC) {
        float acc = lb2[t];
        #pragma unroll 8
        for (int j = 0; j < HD; j++) acc += h[j] * lw2[j * CC + t];
        lg[t] = acc;
    }
    __syncthreads();
    if (t == 0) {
        float m = -1e30f;
        for (int c = 0; c < CC; c++) m = fmaxf(m, lg[c]);
        float s = 0.f;
        for (int c = 0; c < CC; c++) s += expf(lg[c] - m);
        red[0] = m; red[1] = logf(s);
    }
    __syncthreads();
    if (t < CC) op[p * CC + t] = lg[t] - red[0] - red[1];
}

// out = log_softmax(x_rel @ out_proto), warp per node
__global__ void k_out(const float* __restrict__ xrel, const float* __restrict__ proto,
                      float* __restrict__ out)
{
    __shared__ float sp[PP * CC];   // 5120 floats
    __shared__ float srow[8][PP];
    int tid = threadIdx.x;
    for (int i = tid; i < PP * CC; i += 256) sp[i] = proto[i];
    int warp = tid >> 5, lane = tid & 31;
    int node = blockIdx.x * 8 + warp;
    if (node < NN) {
        float4 v = *(const float4*)(xrel + (size_t)node * PP + lane * 4);
        *(float4*)&srow[warp][lane * 4] = v;
    }
    __syncthreads();
    if (node >= NN) return;

    const float* r = srow[warp];
    int c2 = 32 + (lane & 7);
    float a0 = 0.f, a1 = 0.f;
    #pragma unroll 8
    for (int p = 0; p < PP; p++) {
        float x = r[p];
        a0 += x * sp[p * CC + lane];
        a1 += x * sp[p * CC + c2];
    }
    float m = a0;
    if (lane < 8) m = fmaxf(m, a1);
    #pragma unroll
    for (int off = 16; off; off >>= 1) m = fmaxf(m, __shfl_xor_sync(~0u, m, off));
    float se = expf(a0 - m) + ((lane < 8) ? expf(a1 - m) : 0.f);
    #pragma unroll
    for (int off = 16; off; off >>= 1) se += __shfl_xor_sync(~0u, se, off);
    float lse = m + logf(se);
    out[(size_t)node * CC + lane] = a0 - lse;
    if (lane < 8) out[(size_t)node * CC + 32 + lane] = a1 - lse;
}

// ---------------------------------------------------------------------------
// launch
// ---------------------------------------------------------------------------
extern "C" void kernel_launch(void* const* d_in, const int* in_sizes, int n_in,
                              void* d_out, int out_size)
{
    const float* x    = (const float*)d_in[0];
    const int*   ei   = (const int*)  d_in[1];
    const int*   prot = (const int*)  d_in[2];
    const float* W0   = (const float*)d_in[3];
    const float* b0   = (const float*)d_in[4];
    const float* Wh   = (const float*)d_in[5];
    const float* bh   = (const float*)d_in[6];
    const float* lw1  = (const float*)d_in[7];
    const float* lb1  = (const float*)d_in[8];
    const float* lw2  = (const float*)d_in[9];
    const float* lb2  = (const float*)d_in[10];

    float* out   = (float*)d_out;                      // [N, C]
    float* xrel  = out + (size_t)NN * CC;              // [N, P]
    float* oprot = xrel + (size_t)NN * PP;             // [P, C]

    // resolve device-global addresses for kernels that take pointers
    float *pA, *pB, *pAnch;
    cudaGetSymbolAddress((void**)&pA, g_A);
    cudaGetSymbolAddress((void**)&pB, g_B);
    cudaGetSymbolAddress((void**)&pAnch, g_anchors);

    const int TB = 256;
    dim3 gN((NN + TB - 1) / TB);
    dim3 gE((EE + TB - 1) / TB);
    dim3 gGemm((NN + 127) / 128);
    dim3 gWarp8((NN + 7) / 8);

    // --- graph preprocessing (rebuilt every call; deterministic work) ---
    k_zero_deg<<<gN, TB>>>();
    k_deg<<<gE, TB>>>(ei);
    k_dinv<<<gN, TB>>>();
    k_rowbeg<<<gN, TB>>>();
    k_fill<<<gE, TB>>>(ei);

    // --- layer 0: h = x @ W0 ; aggregate ---
    sgemm_n128<false, false, 0><<<gGemm, 256>>>(x, W0, pA, NN, FIN);
    k_agg<<<gWarp8, 256>>>(pA, b0, pB);

    // --- layer 1: h = relu(g) @ Wh[0] ; aggregate ---
    sgemm_n128<true, false, 0><<<gGemm, 256>>>(pB, Wh, pA, NN, HD);
    k_agg<<<gWarp8, 256>>>(pA, bh, pB);

    // --- layer 2: h = relu(g) @ Wh[1] ; aggregate ---
    sgemm_n128<true, false, 0><<<gGemm, 256>>>(pB, Wh + HD * HD, pA, NN, HD);
    k_agg<<<gWarp8, 256>>>(pA, bh + HD, pB);

    // --- L2 normalize rows: hn in g_A ---
    k_rownorm<<<gWarp8, 256>>>(pB, pA);

    // --- anchors, proto head ---
    k_anchors<<<PP, HD>>>(pA, prot);
    k_proto_hp<<<PP, HD>>>(lw1, lb1);
    k_proto_out<<<PP, 64>>>(lw2, lb2, oprot);

    // --- x_rel = (hn @ anchors^T + 1) * 0.5 ---
    sgemm_n128<false, true, 1><<<gGemm, 256>>>(pA, pAnch, xrel, NN, HD);

    // --- out = log_softmax(x_rel @ out_proto) ---
    k_out<<<gWarp8, 256>>>(xrel, oprot, out);
}

// round 6
// speedup vs baseline: 1.2919x; 1.0469x over previous
#include <cuda_runtime.h>
#include <cuda_bf16.h>
#include <math.h>
#include <stdint.h>

// Problem constants (fixed by the reference)
#define NN   50000      // nodes
#define EE   1600000    // edges
#define FIN  256
#define HD   128        // hidden
#define CC   40         // classes
#define PP   128        // prototypes

// ---------------------------------------------------------------------------
// Scratch (static device globals; no allocation in kernel_launch)
// ---------------------------------------------------------------------------
__device__ __align__(16) float g_A[(size_t)NN * HD];     // GEMM output / hn
__device__ __align__(16) float g_B[(size_t)NN * HD];     // aggregation output
__device__ int   g_deg[NN];
__device__ float g_dinv[NN];
__device__ int   g_rowptr[NN];        // segment begin (unordered CSR)
__device__ int   g_cursor[NN];        // fill cursor; == segment end after k_fill
__device__ int   g_total;
__device__ int   g_csrc[EE];
__device__ float g_cw[EE];
__device__ __align__(16) float g_anchors[PP * HD];
__device__ __align__(16) float g_hp[PP * HD];

// ---------------------------------------------------------------------------
// bf16 split: x = hi + lo (both bf16); packs (x,y) pairs into u32 (x=low half)
// ---------------------------------------------------------------------------
__device__ __forceinline__ void split2(float x, float y, uint32_t& hi, uint32_t& lo) {
    __nv_bfloat162 h = __floats2bfloat162_rn(x, y);
    float hx = __bfloat162float(__low2bfloat16(h));
    float hy = __bfloat162float(__high2bfloat16(h));
    __nv_bfloat162 l = __floats2bfloat162_rn(x - hx, y - hy);
    hi = *reinterpret_cast<uint32_t*>(&h);
    lo = *reinterpret_cast<uint32_t*>(&l);
}

// mma.sync m16n8k16 row.col bf16 -> f32 accumulate (sm_80+ baseline ISA)
__device__ __forceinline__ void mma16816(float* c, const uint32_t* a, const uint32_t* b) {
    asm volatile(
        "mma.sync.aligned.m16n8k16.row.col.f32.bf16.bf16.f32 "
        "{%0,%1,%2,%3}, {%4,%5,%6,%7}, {%8,%9}, {%0,%1,%2,%3};"
        : "+f"(c[0]), "+f"(c[1]), "+f"(c[2]), "+f"(c[3])
        : "r"(a[0]), "r"(a[1]), "r"(a[2]), "r"(a[3]),
          "r"(b[0]), "r"(b[1]));
}

// Fragment-order SMEM index math (u32 units).
// A element = bf16 pair (k=2p, 2p+1) of row r. Fragment layout per the PTX
// m16n8k16 a-frag mapping: a0 (r8,c), a1 (r8+8,c), a2 (r8,c+8), a3 (r8+8,c+8).
__device__ __forceinline__ int a_idx(int r, int p) {
    int s = p >> 3, q = p & 7;
    return (((s << 3) | (r >> 4)) << 7)                 // (s*8 + mtile16) * 128
         + ((((r & 7) << 2) | (q & 3)) << 2)            // lane * 4
         + (((q >> 2) << 1) | ((r >> 3) & 1));          // reg
}
// B element = bf16 pair (k=2p,2p+1) at col n. b0 k<8, b1 k>=8.
__device__ __forceinline__ int b_idx(int n, int p) {
    int s = p >> 3, q = p & 7;
    return (((s << 4) | (n >> 3)) << 6)                 // (s*16 + ntile8) * 64
         + ((((n & 7) << 2) | (q & 3)) << 1)            // lane * 2
         + (q >> 2);                                    // reg
}

// ---------------------------------------------------------------------------
// Graph preprocessing
// ---------------------------------------------------------------------------
__global__ void k_zero_deg() {
    int i = blockIdx.x * blockDim.x + threadIdx.x;
    if (i < NN) g_deg[i] = 0;
    if (i == 0) g_total = 0;
}
__global__ void k_deg(const int* __restrict__ ei) {
    int e = blockIdx.x * blockDim.x + threadIdx.x;
    if (e < EE) atomicAdd(&g_deg[ei[EE + e]], 1);
}
__global__ void k_dinv() {
    int i = blockIdx.x * blockDim.x + threadIdx.x;
    if (i < NN) g_dinv[i] = rsqrtf((float)(g_deg[i] + 1));
}
__global__ void k_rowbeg() {
    int i = blockIdx.x * blockDim.x + threadIdx.x;
    if (i < NN) {
        int d = g_deg[i];
        int beg = atomicAdd(&g_total, d);
        g_rowptr[i] = beg;
        g_cursor[i] = beg;
    }
}
__global__ void k_fill(const int* __restrict__ ei) {
    int e = blockIdx.x * blockDim.x + threadIdx.x;
    if (e >= EE) return;
    int s = ei[e];
    int d = ei[EE + e];
    int pos = atomicAdd(&g_cursor[d], 1);
    g_csrc[pos] = s;
    g_cw[pos]   = g_dinv[s];
}

// ---------------------------------------------------------------------------
// bf16x3 HMMA GEMM: C[M x 128] = op(A)[M x K] @ W
//   B_NK = false: W is [K, 128] row-major (transpose-loaded into [n][k])
//   B_NK = true : W is [128, K] row-major (already N-major, e.g. anchors)
// K multiple of 64. EPI: 0 none, 1 = (v+1)*0.5
// SMEM (u32): AHI[4096] ALO[4096] BHI[4096] BLO[4096] = 64KB
// ---------------------------------------------------------------------------
#define HG_SMEM 65536

template<bool RELU_A, bool B_NK, int EPI>
__global__ __launch_bounds__(256, 1)
void k_hgemm(const float* __restrict__ A, const float* __restrict__ Bm,
             float* __restrict__ Cm, int M, int K)
{
    extern __shared__ __align__(16) uint32_t smem[];
    uint32_t* sAhi = smem;
    uint32_t* sAlo = smem + 4096;
    uint32_t* sBhi = smem + 8192;
    uint32_t* sBlo = smem + 12288;

    int tid = threadIdx.x;
    int wid = tid >> 5, lane = tid & 31;
    int wm = wid & 3;          // warp row (32 rows each)
    int wn = wid >> 2;         // warp col (64 cols each)
    int row0 = blockIdx.x * 128;

    float acc[2][8][4];
    #pragma unroll
    for (int a = 0; a < 2; a++)
        #pragma unroll
        for (int b = 0; b < 8; b++)
            #pragma unroll
            for (int c = 0; c < 4; c++) acc[a][b][c] = 0.f;

    int nchunks = K >> 6;
    for (int ch = 0; ch < nchunks; ch++) {
        int kbase = ch << 6;

        // ---- A: 128 rows x 64 k, split to bf16 hi/lo in fragment order ----
        {
            int r = tid >> 1;
            int k4b = (tid & 1) * 8;
            const float* arow = A + (size_t)(row0 + r) * K + kbase;
            bool valid = (row0 + r) < M;
            #pragma unroll
            for (int i = 0; i < 8; i++) {
                int k = (k4b + i) * 4;
                float4 v = make_float4(0.f, 0.f, 0.f, 0.f);
                if (valid) v = *(const float4*)(arow + k);
                if (RELU_A) {
                    v.x = fmaxf(v.x, 0.f); v.y = fmaxf(v.y, 0.f);
                    v.z = fmaxf(v.z, 0.f); v.w = fmaxf(v.w, 0.f);
                }
                uint32_t h0, l0, h1, l1;
                split2(v.x, v.y, h0, l0);
                split2(v.z, v.w, h1, l1);
                int p = k >> 1;
                int i0 = a_idx(r, p), i1 = a_idx(r, p + 1);
                sAhi[i0] = h0; sAlo[i0] = l0;
                sAhi[i1] = h1; sAlo[i1] = l1;
            }
        }
        // ---- B: build [n][k] bf16 pairs (pair along k) ----
        if (B_NK) {
            int n = tid >> 1;
            int k4b = (tid & 1) * 8;
            const float* brow = Bm + (size_t)n * K + kbase;
            #pragma unroll
            for (int i = 0; i < 8; i++) {
                int k = (k4b + i) * 4;
                float4 v = *(const float4*)(brow + k);
                uint32_t h0, l0, h1, l1;
                split2(v.x, v.y, h0, l0);
                split2(v.z, v.w, h1, l1);
                int p = k >> 1;
                int i0 = b_idx(n, p), i1 = b_idx(n, p + 1);
                sBhi[i0] = h0; sBlo[i0] = l0;
                sBhi[i1] = h1; sBlo[i1] = l1;
            }
        } else {
            // W[K][128]: pair rows (2kp, 2kp+1)
            int kp = tid >> 3;                 // kpair 0..31
            int nb = (tid & 7) * 16;
            const float* r0p = Bm + (size_t)(kbase + 2 * kp) * 128;
            const float* r1p = r0p + 128;
            #pragma unroll
            for (int i = 0; i < 4; i++) {
                int n = nb + i * 4;
                float4 a = *(const float4*)(r0p + n);
                float4 b = *(const float4*)(r1p + n);
                uint32_t h, l;
                split2(a.x, b.x, h, l); { int ix = b_idx(n + 0, kp); sBhi[ix] = h; sBlo[ix] = l; }
                split2(a.y, b.y, h, l); { int ix = b_idx(n + 1, kp); sBhi[ix] = h; sBlo[ix] = l; }
                split2(a.z, b.z, h, l); { int ix = b_idx(n + 2, kp); sBhi[ix] = h; sBlo[ix] = l; }
                split2(a.w, b.w, h, l); { int ix = b_idx(n + 3, kp); sBhi[ix] = h; sBlo[ix] = l; }
            }
        }
        __syncthreads();

        // ---- MMA mainloop: 4 k16-steps ----
        #pragma unroll
        for (int s = 0; s < 4; s++) {
            uint4 ah0 = *(const uint4*)(sAhi + (((s << 3) | (wm * 2 + 0)) << 7) + (lane << 2));
            uint4 ah1 = *(const uint4*)(sAhi + (((s << 3) | (wm * 2 + 1)) << 7) + (lane << 2));
            uint4 al0 = *(const uint4*)(sAlo + (((s << 3) | (wm * 2 + 0)) << 7) + (lane << 2));
            uint4 al1 = *(const uint4*)(sAlo + (((s << 3) | (wm * 2 + 1)) << 7) + (lane << 2));
            #pragma unroll
            for (int j = 0; j < 8; j++) {
                int nt = wn * 8 + j;
                uint2 bh = *(const uint2*)(sBhi + (((s << 4) | nt) << 6) + (lane << 1));
                uint2 bl = *(const uint2*)(sBlo + (((s << 4) | nt) << 6) + (lane << 1));
                mma16816(acc[0][j], (const uint32_t*)&ah0, (const uint32_t*)&bh);
                mma16816(acc[0][j], (const uint32_t*)&ah0, (const uint32_t*)&bl);
                mma16816(acc[0][j], (const uint32_t*)&al0, (const uint32_t*)&bh);
                mma16816(acc[1][j], (const uint32_t*)&ah1, (const uint32_t*)&bh);
                mma16816(acc[1][j], (const uint32_t*)&ah1, (const uint32_t*)&bl);
                mma16816(acc[1][j], (const uint32_t*)&al1, (const uint32_t*)&bh);
            }
        }
        __syncthreads();
    }

    // ---- epilogue: c0,c1 at (r, c..c+1); c2,c3 at (r+8, c..c+1) ----
    int rbase = row0 + wm * 32 + (lane >> 2);
    int cbase = wn * 64 + (lane & 3) * 2;
    #pragma unroll
    for (int mt = 0; mt < 2; mt++) {
        #pragma unroll
        for (int j = 0; j < 8; j++) {
            int rr = rbase + mt * 16;
            int cc = cbase + j * 8;
            float2 v0 = make_float2(acc[mt][j][0], acc[mt][j][1]);
            float2 v1 = make_float2(acc[mt][j][2], acc[mt][j][3]);
            if (EPI == 1) {
                v0.x = (v0.x + 1.f) * 0.5f; v0.y = (v0.y + 1.f) * 0.5f;
                v1.x = (v1.x + 1.f) * 0.5f; v1.y = (v1.y + 1.f) * 0.5f;
            }
            if (rr < M)     *(float2*)(Cm + (size_t)rr * 128 + cc) = v0;
            if (rr + 8 < M) *(float2*)(Cm + (size_t)(rr + 8) * 128 + cc) = v1;
        }
    }
}

// ---------------------------------------------------------------------------
// CSR aggregation: g[i,:] = sum_{e: dst=i} dinv[src]*dinv[i]*h[src,:]
//                           + dinv[i]^2 * h[i,:] + bias
// ---------------------------------------------------------------------------
__global__ void k_agg(const float* __restrict__ h, const float* __restrict__ bias,
                      float* __restrict__ g)
{
    int warp = threadIdx.x >> 5, lane = threadIdx.x & 31;
    int node = blockIdx.x * 8 + warp;
    if (node >= NN) return;

    float di = g_dinv[node];
    float4 b  = *(const float4*)(bias + lane * 4);
    float4 hv = *(const float4*)(h + (size_t)node * 128 + lane * 4);
    float w0 = di * di;
    float4 acc = make_float4(b.x + w0 * hv.x, b.y + w0 * hv.y,
                             b.z + w0 * hv.z, b.w + w0 * hv.w);

    int beg = g_rowptr[node], end = g_cursor[node];
    #pragma unroll 4
    for (int e = beg; e < end; e++) {
        int   s = g_csrc[e];
        float w = g_cw[e] * di;
        float4 x = *(const float4*)(h + (size_t)s * 128 + lane * 4);
        acc.x += w * x.x; acc.y += w * x.y;
        acc.z += w * x.z; acc.w += w * x.w;
    }
    *(float4*)(g + (size_t)node * 128 + lane * 4) = acc;
}

// ---------------------------------------------------------------------------
// Row L2 normalize
// ---------------------------------------------------------------------------
__global__ void k_rownorm(const float* __restrict__ h, float* __restrict__ hn) {
    int warp = threadIdx.x >> 5, lane = threadIdx.x & 31;
    int node = blockIdx.x * 8 + warp;
    if (node >= NN) return;
    float4 v = *(const float4*)(h + (size_t)node * 128 + lane * 4);
    float s = v.x * v.x + v.y * v.y + v.z * v.z + v.w * v.w;
    #pragma unroll
    for (int off = 16; off; off >>= 1) s += __shfl_xor_sync(~0u, s, off);
    float inv = 1.0f / sqrtf(s);
    v.x *= inv; v.y *= inv; v.z *= inv; v.w *= inv;
    *(float4*)(hn + (size_t)node * 128 + lane * 4) = v;
}

__global__ void k_anchors(const float* __restrict__ hn, const int* __restrict__ prot) {
    int p = blockIdx.x, t = threadIdx.x;
    g_anchors[p * HD + t] = hn[(size_t)prot[p] * HD + t];
}

__global__ void k_proto_hp(const float* __restrict__ lw1, const float* __restrict__ lb1) {
    __shared__ float a[HD];
    int p = blockIdx.x, j = threadIdx.x;
    a[j] = g_anchors[p * HD + j];
    __syncthreads();
    float acc = lb1[j];
    #pragma unroll 8
    for (int k = 0; k < HD; k++) acc += a[k] * lw1[k * HD + j];
    g_hp[p * HD + j] = fmaxf(acc, 0.f);
}

__global__ void k_proto_out(const float* __restrict__ lw2, const float* __restrict__ lb2,
                            float* __restrict__ op)
{
    __shared__ float h[HD];
    __shared__ float lg[CC];
    __shared__ float red[2];
    int p = blockIdx.x, t = threadIdx.x;   // 64 threads
    h[t] = g_hp[p * HD + t];
    h[t + 64] = g_hp[p * HD + 64 + t];
    __syncthreads();
    if (t < CC) {
        float acc = lb2[t];
        #pragma unroll 8
        for (int j = 0; j < HD; j++) acc += h[j] * lw2[j * CC + t];
        lg[t] = acc;
    }
    __syncthreads();
    if (t == 0) {
        float m = -1e30f;
        for (int c = 0; c < CC; c++) m = fmaxf(m, lg[c]);
        float s = 0.f;
        for (int c = 0; c < CC; c++) s += expf(lg[c] - m);
        red[0] = m; red[1] = logf(s);
    }
    __syncthreads();
    if (t < CC) op[p * CC + t] = lg[t] - red[0] - red[1];
}

__global__ void k_out(const float* __restrict__ xrel, const float* __restrict__ proto,
                      float* __restrict__ out)
{
    __shared__ float sp[PP * CC];
    __shared__ float srow[8][PP];
    int tid = threadIdx.x;
    for (int i = tid; i < PP * CC; i += 256) sp[i] = proto[i];
    int warp = tid >> 5, lane = tid & 31;
    int node = blockIdx.x * 8 + warp;
    if (node < NN) {
        float4 v = *(const float4*)(xrel + (size_t)node * PP + lane * 4);
        *(float4*)&srow[warp][lane * 4] = v;
    }
    __syncthreads();
    if (node >= NN) return;

    const float* r = srow[warp];
    int c2 = 32 + (lane & 7);
    float a0 = 0.f, a1 = 0.f;
    #pragma unroll 8
    for (int p = 0; p < PP; p++) {
        float x = r[p];
        a0 += x * sp[p * CC + lane];
        a1 += x * sp[p * CC + c2];
    }
    float m = a0;
    if (lane < 8) m = fmaxf(m, a1);
    #pragma unroll
    for (int off = 16; off; off >>= 1) m = fmaxf(m, __shfl_xor_sync(~0u, m, off));
    float se = expf(a0 - m) + ((lane < 8) ? expf(a1 - m) : 0.f);
    #pragma unroll
    for (int off = 16; off; off >>= 1) se += __shfl_xor_sync(~0u, se, off);
    float lse = m + logf(se);
    out[(size_t)node * CC + lane] = a0 - lse;
    if (lane < 8) out[(size_t)node * CC + 32 + lane] = a1 - lse;
}

// ---------------------------------------------------------------------------
// launch
// ---------------------------------------------------------------------------
extern "C" void kernel_launch(void* const* d_in, const int* in_sizes, int n_in,
                              void* d_out, int out_size)
{
    const float* x    = (const float*)d_in[0];
    const int*   ei   = (const int*)  d_in[1];
    const int*   prot = (const int*)  d_in[2];
    const float* W0   = (const float*)d_in[3];
    const float* b0   = (const float*)d_in[4];
    const float* Wh   = (const float*)d_in[5];
    const float* bh   = (const float*)d_in[6];
    const float* lw1  = (const float*)d_in[7];
    const float* lb1  = (const float*)d_in[8];
    const float* lw2  = (const float*)d_in[9];
    const float* lb2  = (const float*)d_in[10];

    float* out   = (float*)d_out;                      // [N, C]
    float* xrel  = out + (size_t)NN * CC;              // [N, P]
    float* oprot = xrel + (size_t)NN * PP;             // [P, C]

    float *pA, *pB, *pAnch;
    cudaGetSymbolAddress((void**)&pA, g_A);
    cudaGetSymbolAddress((void**)&pB, g_B);
    cudaGetSymbolAddress((void**)&pAnch, g_anchors);

    // 64KB dynamic smem opt-in (host attr, not a stream op)
    cudaFuncSetAttribute(k_hgemm<false, false, 0>,
                         cudaFuncAttributeMaxDynamicSharedMemorySize, HG_SMEM);
    cudaFuncSetAttribute(k_hgemm<true, false, 0>,
                         cudaFuncAttributeMaxDynamicSharedMemorySize, HG_SMEM);
    cudaFuncSetAttribute(k_hgemm<false, true, 1>,
                         cudaFuncAttributeMaxDynamicSharedMemorySize, HG_SMEM);

    const int TB = 256;
    dim3 gN((NN + TB - 1) / TB);
    dim3 gE((EE + TB - 1) / TB);
    dim3 gGemm((NN + 127) / 128);
    dim3 gWarp8((NN + 7) / 8);

    // --- graph preprocessing ---
    k_zero_deg<<<gN, TB>>>();
    k_deg<<<gE, TB>>>(ei);
    k_dinv<<<gN, TB>>>();
    k_rowbeg<<<gN, TB>>>();
    k_fill<<<gE, TB>>>(ei);

    // --- layer 0: h = x @ W0 ; aggregate ---
    k_hgemm<false, false, 0><<<gGemm, 256, HG_SMEM>>>(x, W0, pA, NN, FIN);
    k_agg<<<gWarp8, 256>>>(pA, b0, pB);

    // --- layer 1 ---
    k_hgemm<true, false, 0><<<gGemm, 256, HG_SMEM>>>(pB, Wh, pA, NN, HD);
    k_agg<<<gWarp8, 256>>>(pA, bh, pB);

    // --- layer 2 ---
    k_hgemm<true, false, 0><<<gGemm, 256, HG_SMEM>>>(pB, Wh + HD * HD, pA, NN, HD);
    k_agg<<<gWarp8, 256>>>(pA, bh + HD, pB);

    // --- L2 normalize rows ---
    k_rownorm<<<gWarp8, 256>>>(pB, pA);

    // --- anchors, proto head ---
    k_anchors<<<PP, HD>>>(pA, prot);
    k_proto_hp<<<PP, HD>>>(lw1, lb1);
    k_proto_out<<<PP, 64>>>(lw2, lb2, oprot);

    // --- x_rel = (hn @ anchors^T + 1) * 0.5 ---
    k_hgemm<false, true, 1><<<gGemm, 256, HG_SMEM>>>(pA, pAnch, xrel, NN, HD);

    // --- out = log_softmax(x_rel @ out_proto) ---
    k_out<<<gWarp8, 256>>>(xrel, oprot, out);
}

// round 7
// speedup vs baseline: 1.3661x; 1.0574x over previous
#include <cuda_runtime.h>
#include <cuda_bf16.h>
#include <cuda_fp16.h>
#include <math.h>
#include <stdint.h>

// Problem constants (fixed by the reference)
#define NN   50000      // nodes
#define EE   1600000    // edges
#define FIN  256
#define HD   128        // hidden
#define CC   40         // classes
#define PP   128        // prototypes

// ---------------------------------------------------------------------------
// Scratch (static device globals; no allocation in kernel_launch)
// ---------------------------------------------------------------------------
__device__ __align__(16) __half   g_H[(size_t)NN * 128];    // fp16 wire (GEMM out)
__device__ __align__(16) uint32_t g_Phi[(size_t)NN * 64];   // bf16 hi pairs (agg out)
__device__ __align__(16) uint32_t g_Plo[(size_t)NN * 64];   // bf16 lo pairs
__device__ __align__(16) float    g_B[(size_t)NN * 128];    // agg2 out fp32
__device__ __align__(16) float    g_A[(size_t)NN * 128];    // hn fp32
__device__ __align__(16) uint32_t g_W0hi[128 * 128], g_W0lo[128 * 128];
__device__ __align__(16) uint32_t g_W1hi[128 * 64],  g_W1lo[128 * 64];
__device__ __align__(16) uint32_t g_W2hi[128 * 64],  g_W2lo[128 * 64];
__device__ __align__(16) uint32_t g_AncHi[128 * 64], g_AncLo[128 * 64];
__device__ __align__(16) float    g_anchors[PP * HD];
__device__ __align__(16) float    g_hp[PP * HD];
__device__ int   g_deg[NN];
__device__ float g_dinv[NN];
__device__ int   g_rowptr[NN];
__device__ int   g_cursor[NN];
__device__ int   g_total;
__device__ int   g_csrc[EE];
__device__ float g_cw[EE];

// ---------------------------------------------------------------------------
// bf16 split: x = hi + lo (both bf16); packs (x,y) pairs into u32 (x=low half)
// ---------------------------------------------------------------------------
__device__ __forceinline__ void split2(float x, float y, uint32_t& hi, uint32_t& lo) {
    __nv_bfloat162 h = __floats2bfloat162_rn(x, y);
    float hx = __bfloat162float(__low2bfloat16(h));
    float hy = __bfloat162float(__high2bfloat16(h));
    __nv_bfloat162 l = __floats2bfloat162_rn(x - hx, y - hy);
    hi = *reinterpret_cast<uint32_t*>(&h);
    lo = *reinterpret_cast<uint32_t*>(&l);
}

// mma.sync m16n8k16 row.col bf16 -> f32 accumulate
__device__ __forceinline__ void mma16816(float* c, const uint32_t* a, const uint32_t* b) {
    asm volatile(
        "mma.sync.aligned.m16n8k16.row.col.f32.bf16.bf16.f32 "
        "{%0,%1,%2,%3}, {%4,%5,%6,%7}, {%8,%9}, {%0,%1,%2,%3};"
        : "+f"(c[0]), "+f"(c[1]), "+f"(c[2]), "+f"(c[3])
        : "r"(a[0]), "r"(a[1]), "r"(a[2]), "r"(a[3]),
          "r"(b[0]), "r"(b[1]));
}

// Fragment-order SMEM index math (u32 units), p = k/2 local to a 64-k chunk.
__device__ __forceinline__ int a_idx(int r, int p) {
    int s = p >> 3, q = p & 7;
    return (((s << 3) | (r >> 4)) << 7)
         + ((((r & 7) << 2) | (q & 3)) << 2)
         + (((q >> 2) << 1) | ((r >> 3) & 1));
}
__device__ __forceinline__ int b_idx(int n, int p) {
    int s = p >> 3, q = p & 7;
    return (((s << 4) | (n >> 3)) << 6)
         + ((((n & 7) << 2) | (q & 3)) << 1)
         + (q >> 2);
}

// ---------------------------------------------------------------------------
// Graph preprocessing
// ---------------------------------------------------------------------------
__global__ void k_zero_deg() {
    int i = blockIdx.x * blockDim.x + threadIdx.x;
    if (i < NN) g_deg[i] = 0;
    if (i == 0) g_total = 0;
}
__global__ void k_deg(const int* __restrict__ ei) {
    int e = blockIdx.x * blockDim.x + threadIdx.x;
    if (e < EE) atomicAdd(&g_deg[ei[EE + e]], 1);
}
__global__ void k_dinv() {
    int i = blockIdx.x * blockDim.x + threadIdx.x;
    if (i < NN) g_dinv[i] = rsqrtf((float)(g_deg[i] + 1));
}
__global__ void k_rowbeg() {
    int i = blockIdx.x * blockDim.x + threadIdx.x;
    if (i < NN) {
        int d = g_deg[i];
        int beg = atomicAdd(&g_total, d);
        g_rowptr[i] = beg;
        g_cursor[i] = beg;
    }
}
__global__ void k_fill(const int* __restrict__ ei) {
    int e = blockIdx.x * blockDim.x + threadIdx.x;
    if (e >= EE) return;
    int s = ei[e];
    int d = ei[EE + e];
    int pos = atomicAdd(&g_cursor[d], 1);
    g_csrc[pos] = s;
    g_cw[pos]   = g_dinv[s];
}

// Convert weight W[K,128] (k-major) to n-major bf16 pair arrays [n][Kp].
__global__ void k_convW(const float* __restrict__ W, uint32_t* __restrict__ hi,
                        uint32_t* __restrict__ lo, int Kpairs) {
    int p = blockIdx.x;     // pair index
    int n = threadIdx.x;    // col
    float a = W[(size_t)(2 * p) * 128 + n];
    float b = W[(size_t)(2 * p + 1) * 128 + n];
    uint32_t h, l;
    split2(a, b, h, l);
    hi[n * Kpairs + p] = h;
    lo[n * Kpairs + p] = l;
}

// ---------------------------------------------------------------------------
// bf16x3 HMMA GEMM: C[M x 128] = A[M x K] @ B^T, B pre-split n-major pairs.
// AMODE 0: A fp32 row-major (split in-kernel); AMODE 1: A pre-split pairs [row][K/2]
// OUTH: write __half wire; else fp32 (+EPI==1: (v+1)*0.5)
// ---------------------------------------------------------------------------
#define HG_SMEM 65536

template<int AMODE, bool OUTH, int EPI>
__global__ __launch_bounds__(256, 1)
void k_hgemm(const float* __restrict__ Af,
             const uint32_t* __restrict__ APhi, const uint32_t* __restrict__ APlo,
             const uint32_t* __restrict__ Bhi_g, const uint32_t* __restrict__ Blo_g,
             float* __restrict__ Cf, __half* __restrict__ Ch, int M, int K)
{
    extern __shared__ __align__(16) uint32_t smem[];
    uint32_t* sAhi = smem;
    uint32_t* sAlo = smem + 4096;
    uint32_t* sBhi = smem + 8192;
    uint32_t* sBlo = smem + 12288;

    int tid = threadIdx.x;
    int wid = tid >> 5, lane = tid & 31;
    int wm = wid & 3;          // warp row (32 rows each)
    int wn = wid >> 2;         // warp col (64 cols each)
    int row0 = blockIdx.x * 128;
    int Kp = K >> 1;

    float acc[2][8][4];
    #pragma unroll
    for (int a = 0; a < 2; a++)
        #pragma unroll
        for (int b = 0; b < 8; b++)
            #pragma unroll
            for (int c = 0; c < 4; c++) acc[a][b][c] = 0.f;

    int nchunks = K >> 6;
    for (int ch = 0; ch < nchunks; ch++) {
        // ---- A chunk ----
        if (AMODE == 0) {
            int r = tid >> 1;
            int k4b = (tid & 1) * 8;
            const float* arow = Af + (size_t)(row0 + r) * K + (ch << 6);
            bool valid = (row0 + r) < M;
            #pragma unroll
            for (int i = 0; i < 8; i++) {
                int k = (k4b + i) * 4;
                float4 v = make_float4(0.f, 0.f, 0.f, 0.f);
                if (valid) v = *(const float4*)(arow + k);
                uint32_t h0, l0, h1, l1;
                split2(v.x, v.y, h0, l0);
                split2(v.z, v.w, h1, l1);
                int p = k >> 1;
                int i0 = a_idx(r, p), i1 = a_idx(r, p + 1);
                sAhi[i0] = h0; sAlo[i0] = l0;
                sAhi[i1] = h1; sAlo[i1] = l1;
            }
        } else {
            int r = tid >> 1, seg = tid & 1;
            bool valid = (row0 + r) < M;
            const uint32_t* ah = APhi + (size_t)(row0 + r) * Kp + ch * 32 + seg * 16;
            const uint32_t* al = APlo + (size_t)(row0 + r) * Kp + ch * 32 + seg * 16;
            #pragma unroll
            for (int i = 0; i < 4; i++) {
                uint4 vh = make_uint4(0, 0, 0, 0), vl = make_uint4(0, 0, 0, 0);
                if (valid) { vh = *(const uint4*)(ah + i * 4); vl = *(const uint4*)(al + i * 4); }
                int pb = seg * 16 + i * 4;
                int i0 = a_idx(r, pb + 0), i1 = a_idx(r, pb + 1);
                int i2 = a_idx(r, pb + 2), i3 = a_idx(r, pb + 3);
                sAhi[i0] = vh.x; sAlo[i0] = vl.x;
                sAhi[i1] = vh.y; sAlo[i1] = vl.y;
                sAhi[i2] = vh.z; sAlo[i2] = vl.z;
                sAhi[i3] = vh.w; sAlo[i3] = vl.w;
            }
        }
        // ---- B chunk: pre-split n-major [n][Kp] ----
        {
            int n = tid >> 1, seg = tid & 1;
            const uint32_t* bh = Bhi_g + (size_t)n * Kp + ch * 32 + seg * 16;
            const uint32_t* bl = Blo_g + (size_t)n * Kp + ch * 32 + seg * 16;
            #pragma unroll
            for (int i = 0; i < 4; i++) {
                uint4 vh = *(const uint4*)(bh + i * 4);
                uint4 vl = *(const uint4*)(bl + i * 4);
                int pb = seg * 16 + i * 4;
                int i0 = b_idx(n, pb + 0), i1 = b_idx(n, pb + 1);
                int i2 = b_idx(n, pb + 2), i3 = b_idx(n, pb + 3);
                sBhi[i0] = vh.x; sBlo[i0] = vl.x;
                sBhi[i1] = vh.y; sBlo[i1] = vl.y;
                sBhi[i2] = vh.z; sBlo[i2] = vl.z;
                sBhi[i3] = vh.w; sBlo[i3] = vl.w;
            }
        }
        __syncthreads();

        // ---- MMA mainloop: 4 k16-steps ----
        #pragma unroll
        for (int s = 0; s < 4; s++) {
            uint4 ah0 = *(const uint4*)(sAhi + (((s << 3) | (wm * 2 + 0)) << 7) + (lane << 2));
            uint4 ah1 = *(const uint4*)(sAhi + (((s << 3) | (wm * 2 + 1)) << 7) + (lane << 2));
            uint4 al0 = *(const uint4*)(sAlo + (((s << 3) | (wm * 2 + 0)) << 7) + (lane << 2));
            uint4 al1 = *(const uint4*)(sAlo + (((s << 3) | (wm * 2 + 1)) << 7) + (lane << 2));
            #pragma unroll
            for (int j = 0; j < 8; j++) {
                int nt = wn * 8 + j;
                uint2 bh = *(const uint2*)(sBhi + (((s << 4) | nt) << 6) + (lane << 1));
                uint2 bl = *(const uint2*)(sBlo + (((s << 4) | nt) << 6) + (lane << 1));
                mma16816(acc[0][j], (const uint32_t*)&ah0, (const uint32_t*)&bh);
                mma16816(acc[0][j], (const uint32_t*)&ah0, (const uint32_t*)&bl);
                mma16816(acc[0][j], (const uint32_t*)&al0, (const uint32_t*)&bh);
                mma16816(acc[1][j], (const uint32_t*)&ah1, (const uint32_t*)&bh);
                mma16816(acc[1][j], (const uint32_t*)&ah1, (const uint32_t*)&bl);
                mma16816(acc[1][j], (const uint32_t*)&al1, (const uint32_t*)&bh);
            }
        }
        __syncthreads();
    }

    // ---- epilogue ----
    int rbase = row0 + wm * 32 + (lane >> 2);
    int cbase = wn * 64 + (lane & 3) * 2;
    #pragma unroll
    for (int mt = 0; mt < 2; mt++) {
        #pragma unroll
        for (int j = 0; j < 8; j++) {
            int rr = rbase + mt * 16;
            int cc = cbase + j * 8;
            if (OUTH) {
                __half2 v0 = __floats2half2_rn(acc[mt][j][0], acc[mt][j][1]);
                __half2 v1 = __floats2half2_rn(acc[mt][j][2], acc[mt][j][3]);
                if (rr < M)     *(__half2*)(Ch + (size_t)rr * 128 + cc) = v0;
                if (rr + 8 < M) *(__half2*)(Ch + (size_t)(rr + 8) * 128 + cc) = v1;
            } else {
                float2 v0 = make_float2(acc[mt][j][0], acc[mt][j][1]);
                float2 v1 = make_float2(acc[mt][j][2], acc[mt][j][3]);
                if (EPI == 1) {
                    v0.x = (v0.x + 1.f) * 0.5f; v0.y = (v0.y + 1.f) * 0.5f;
                    v1.x = (v1.x + 1.f) * 0.5f; v1.y = (v1.y + 1.f) * 0.5f;
                }
                if (rr < M)     *(float2*)(Cf + (size_t)rr * 128 + cc) = v0;
                if (rr + 8 < M) *(float2*)(Cf + (size_t)(rr + 8) * 128 + cc) = v1;
            }
        }
    }
}

// ---------------------------------------------------------------------------
// CSR aggregation over fp16 wire. OUT=0: relu -> bf16 pair arrays (next GEMM A)
//                                 OUT=1: fp32 -> g_B (rownorm input)
// ---------------------------------------------------------------------------
template<int OUT>
__global__ void k_agg(const __half* __restrict__ h, const float* __restrict__ bias)
{
    int warp = threadIdx.x >> 5, lane = threadIdx.x & 31;
    int node = blockIdx.x * 8 + warp;
    if (node >= NN) return;

    float di = g_dinv[node];
    float4 b = *(const float4*)(bias + lane * 4);
    uint2 hv = *(const uint2*)(h + (size_t)node * 128 + lane * 4);
    float2 s01 = __half22float2(*reinterpret_cast<__half2*>(&hv.x));
    float2 s23 = __half22float2(*reinterpret_cast<__half2*>(&hv.y));
    float w0 = di * di;
    float4 acc = make_float4(b.x + w0 * s01.x, b.y + w0 * s01.y,
                             b.z + w0 * s23.x, b.w + w0 * s23.y);

    int beg = g_rowptr[node], end = g_cursor[node];
    #pragma unroll 4
    for (int e = beg; e < end; e++) {
        int   s = g_csrc[e];
        float w = g_cw[e] * di;
        uint2 xv = *(const uint2*)(h + (size_t)s * 128 + lane * 4);
        float2 x01 = __half22float2(*reinterpret_cast<__half2*>(&xv.x));
        float2 x23 = __half22float2(*reinterpret_cast<__half2*>(&xv.y));
        acc.x += w * x01.x; acc.y += w * x01.y;
        acc.z += w * x23.x; acc.w += w * x23.y;
    }
    if (OUT == 0) {
        acc.x = fmaxf(acc.x, 0.f); acc.y = fmaxf(acc.y, 0.f);
        acc.z = fmaxf(acc.z, 0.f); acc.w = fmaxf(acc.w, 0.f);
        uint32_t h0, l0, h1, l1;
        split2(acc.x, acc.y, h0, l0);
        split2(acc.z, acc.w, h1, l1);
        *(uint2*)(g_Phi + (size_t)node * 64 + lane * 2) = make_uint2(h0, h1);
        *(uint2*)(g_Plo + (size_t)node * 64 + lane * 2) = make_uint2(l0, l1);
    } else {
        *(float4*)(g_B + (size_t)node * 128 + lane * 4) = acc;
    }
}

// ---------------------------------------------------------------------------
// Row L2 normalize: hn fp32 -> g_A, and bf16 pairs -> g_Phi/g_Plo (xrel GEMM A)
// ---------------------------------------------------------------------------
__global__ void k_rownorm() {
    int warp = threadIdx.x >> 5, lane = threadIdx.x & 31;
    int node = blockIdx.x * 8 + warp;
    if (node >= NN) return;
    float4 v = *(const float4*)(g_B + (size_t)node * 128 + lane * 4);
    float s = v.x * v.x + v.y * v.y + v.z * v.z + v.w * v.w;
    #pragma unroll
    for (int off = 16; off; off >>= 1) s += __shfl_xor_sync(~0u, s, off);
    float inv = 1.0f / sqrtf(s);
    v.x *= inv; v.y *= inv; v.z *= inv; v.w *= inv;
    *(float4*)(g_A + (size_t)node * 128 + lane * 4) = v;
    uint32_t h0, l0, h1, l1;
    split2(v.x, v.y, h0, l0);
    split2(v.z, v.w, h1, l1);
    *(uint2*)(g_Phi + (size_t)node * 64 + lane * 2) = make_uint2(h0, h1);
    *(uint2*)(g_Plo + (size_t)node * 64 + lane * 2) = make_uint2(l0, l1);
}

__global__ void k_anchors(const int* __restrict__ prot) {
    int p = blockIdx.x, t = threadIdx.x;   // 128 threads
    int src = prot[p];
    g_anchors[p * HD + t] = g_A[(size_t)src * HD + t];
    if (t < 64) {
        g_AncHi[p * 64 + t] = g_Phi[(size_t)src * 64 + t];
        g_AncLo[p * 64 + t] = g_Plo[(size_t)src * 64 + t];
    }
}

__global__ void k_proto_hp(const float* __restrict__ lw1, const float* __restrict__ lb1) {
    __shared__ float a[HD];
    int p = blockIdx.x, j = threadIdx.x;
    a[j] = g_anchors[p * HD + j];
    __syncthreads();
    float acc = lb1[j];
    #pragma unroll 8
    for (int k = 0; k < HD; k++) acc += a[k] * lw1[k * HD + j];
    g_hp[p * HD + j] = fmaxf(acc, 0.f);
}

__global__ void k_proto_out(const float* __restrict__ lw2, const float* __restrict__ lb2,
                            float* __restrict__ op)
{
    __shared__ float h[HD];
    __shared__ float lg[CC];
    __shared__ float red[2];
    int p = blockIdx.x, t = threadIdx.x;   // 64 threads
    h[t] = g_hp[p * HD + t];
    h[t + 64] = g_hp[p * HD + 64 + t];
    __syncthreads();
    if (t < CC) {
        float acc = lb2[t];
        #pragma unroll 8
        for (int j = 0; j < HD; j++) acc += h[j] * lw2[j * CC + t];
        lg[t] = acc;
    }
    __syncthreads();
    if (t == 0) {
        float m = -1e30f;
        for (int c = 0; c < CC; c++) m = fmaxf(m, lg[c]);
        float s = 0.f;
        for (int c = 0; c < CC; c++) s += expf(lg[c] - m);
        red[0] = m; red[1] = logf(s);
    }
    __syncthreads();
    if (t < CC) op[p * CC + t] = lg[t] - red[0] - red[1];
}

__global__ void k_out(const float* __restrict__ xrel, const float* __restrict__ proto,
                      float* __restrict__ out)
{
    __shared__ float sp[PP * CC];
    __shared__ float srow[8][PP];
    int tid = threadIdx.x;
    for (int i = tid; i < PP * CC; i += 256) sp[i] = proto[i];
    int warp = tid >> 5, lane = tid & 31;
    int node = blockIdx.x * 8 + warp;
    if (node < NN) {
        float4 v = *(const float4*)(xrel + (size_t)node * PP + lane * 4);
        *(float4*)&srow[warp][lane * 4] = v;
    }
    __syncthreads();
    if (node >= NN) return;

    const float* r = srow[warp];
    int c2 = 32 + (lane & 7);
    float a0 = 0.f, a1 = 0.f;
    #pragma unroll 8
    for (int p = 0; p < PP; p++) {
        float x = r[p];
        a0 += x * sp[p * CC + lane];
        a1 += x * sp[p * CC + c2];
    }
    float m = a0;
    if (lane < 8) m = fmaxf(m, a1);
    #pragma unroll
    for (int off = 16; off; off >>= 1) m = fmaxf(m, __shfl_xor_sync(~0u, m, off));
    float se = expf(a0 - m) + ((lane < 8) ? expf(a1 - m) : 0.f);
    #pragma unroll
    for (int off = 16; off; off >>= 1) se += __shfl_xor_sync(~0u, se, off);
    float lse = m + logf(se);
    out[(size_t)node * CC + lane] = a0 - lse;
    if (lane < 8) out[(size_t)node * CC + 32 + lane] = a1 - lse;
}

// ---------------------------------------------------------------------------
// launch
// ---------------------------------------------------------------------------
extern "C" void kernel_launch(void* const* d_in, const int* in_sizes, int n_in,
                              void* d_out, int out_size)
{
    const float* x    = (const float*)d_in[0];
    const int*   ei   = (const int*)  d_in[1];
    const int*   prot = (const int*)  d_in[2];
    const float* W0   = (const float*)d_in[3];
    const float* b0   = (const float*)d_in[4];
    const float* Wh   = (const float*)d_in[5];
    const float* bh   = (const float*)d_in[6];
    const float* lw1  = (const float*)d_in[7];
    const float* lb1  = (const float*)d_in[8];
    const float* lw2  = (const float*)d_in[9];
    const float* lb2  = (const float*)d_in[10];

    float* out   = (float*)d_out;                      // [N, C]
    float* xrel  = out + (size_t)NN * CC;              // [N, P]
    float* oprot = xrel + (size_t)NN * PP;             // [P, C]

    __half* pH;
    float *pA;
    uint32_t *pPhi, *pPlo, *pW0h, *pW0l, *pW1h, *pW1l, *pW2h, *pW2l, *pAnH, *pAnL;
    cudaGetSymbolAddress((void**)&pH, g_H);
    cudaGetSymbolAddress((void**)&pA, g_A);
    cudaGetSymbolAddress((void**)&pPhi, g_Phi);
    cudaGetSymbolAddress((void**)&pPlo, g_Plo);
    cudaGetSymbolAddress((void**)&pW0h, g_W0hi);
    cudaGetSymbolAddress((void**)&pW0l, g_W0lo);
    cudaGetSymbolAddress((void**)&pW1h, g_W1hi);
    cudaGetSymbolAddress((void**)&pW1l, g_W1lo);
    cudaGetSymbolAddress((void**)&pW2h, g_W2hi);
    cudaGetSymbolAddress((void**)&pW2l, g_W2lo);
    cudaGetSymbolAddress((void**)&pAnH, g_AncHi);
    cudaGetSymbolAddress((void**)&pAnL, g_AncLo);

    cudaFuncSetAttribute(k_hgemm<0, true, 0>,
                         cudaFuncAttributeMaxDynamicSharedMemorySize, HG_SMEM);
    cudaFuncSetAttribute(k_hgemm<1, true, 0>,
                         cudaFuncAttributeMaxDynamicSharedMemorySize, HG_SMEM);
    cudaFuncSetAttribute(k_hgemm<1, false, 1>,
                         cudaFuncAttributeMaxDynamicSharedMemorySize, HG_SMEM);

    const int TB = 256;
    dim3 gN((NN + TB - 1) / TB);
    dim3 gE((EE + TB - 1) / TB);
    dim3 gGemm((NN + 127) / 128);
    dim3 gWarp8((NN + 7) / 8);

    // --- graph preprocessing ---
    k_zero_deg<<<gN, TB>>>();
    k_deg<<<gE, TB>>>(ei);
    k_dinv<<<gN, TB>>>();
    k_rowbeg<<<gN, TB>>>();
    k_fill<<<gE, TB>>>(ei);

    // --- weight pre-conversion (tiny) ---
    k_convW<<<128, 128>>>(W0, pW0h, pW0l, 128);              // W0: 256x128 -> 128 pairs
    k_convW<<<64, 128>>>(Wh, pW1h, pW1l, 64);                // Wh[0]: 128x128 -> 64 pairs
    k_convW<<<64, 128>>>(Wh + HD * HD, pW2h, pW2l, 64);      // Wh[1]

    // --- layer 0: h = x @ W0 (fp16 wire) ; aggregate -> relu -> bf16 pairs ---
    k_hgemm<0, true, 0><<<gGemm, 256, HG_SMEM>>>(x, nullptr, nullptr, pW0h, pW0l,
                                                 nullptr, pH, NN, FIN);
    k_agg<0><<<gWarp8, 256>>>(pH, b0);

    // --- layer 1 ---
    k_hgemm<1, true, 0><<<gGemm, 256, HG_SMEM>>>(nullptr, pPhi, pPlo, pW1h, pW1l,
                                                 nullptr, pH, NN, HD);
    k_agg<0><<<gWarp8, 256>>>(pH, bh);

    // --- layer 2 ---
    k_hgemm<1, true, 0><<<gGemm, 256, HG_SMEM>>>(nullptr, pPhi, pPlo, pW2h, pW2l,
                                                 nullptr, pH, NN, HD);
    k_agg<1><<<gWarp8, 256>>>(pH, bh + HD);

    // --- L2 normalize: g_B -> g_A fp32 + g_Phi/g_Plo pairs ---
    k_rownorm<<<gWarp8, 256>>>();

    // --- anchors (fp32 + pairs), proto head ---
    k_anchors<<<PP, HD>>>(prot);
    k_proto_hp<<<PP, HD>>>(lw1, lb1);
    k_proto_out<<<PP, 64>>>(lw2, lb2, oprot);

    // --- x_rel = (hn @ anchors^T + 1) * 0.5 ---
    k_hgemm<1, false, 1><<<gGemm, 256, HG_SMEM>>>(nullptr, pPhi, pPlo, pAnH, pAnL,
                                                  xrel, nullptr, NN, HD);

    // --- out = log_softmax(x_rel @ out_proto) ---
    k_out<<<gWarp8, 256>>>(xrel, oprot, out);
}

// round 8
// speedup vs baseline: 1.4229x; 1.0416x over previous
#include <cuda_runtime.h>
#include <cuda_bf16.h>
#include <cuda_fp16.h>
#include <math.h>
#include <stdint.h>

// Problem constants (fixed by the reference)
#define NN   50000      // nodes
#define EE   1600000    // edges
#define FIN  256
#define HD   128        // hidden
#define CC   40         // classes
#define PP   128        // prototypes

// ---------------------------------------------------------------------------
// Scratch (static device globals; no allocation in kernel_launch)
// ---------------------------------------------------------------------------
__device__ __align__(16) __half   g_H[(size_t)NN * 128];    // fp16 wire (GEMM out)
__device__ __align__(16) uint32_t g_Phi[(size_t)NN * 64];   // bf16 hi pairs
__device__ __align__(16) uint32_t g_Plo[(size_t)NN * 64];   // bf16 lo pairs
__device__ __align__(16) float    g_A[(size_t)NN * 128];    // hn fp32
__device__ __align__(16) uint32_t g_W0hi[128 * 128], g_W0lo[128 * 128];
__device__ __align__(16) uint32_t g_W1hi[128 * 64],  g_W1lo[128 * 64];
__device__ __align__(16) uint32_t g_W2hi[128 * 64],  g_W2lo[128 * 64];
__device__ __align__(16) uint32_t g_AncHi[128 * 64], g_AncLo[128 * 64];
__device__ __align__(16) float    g_anchors[PP * HD];
__device__ __align__(16) float    g_hp[PP * HD];
__device__ int   g_deg[NN];
__device__ float g_dinv[NN];
__device__ int   g_rowptr[NN];
__device__ int   g_cursor[NN];
__device__ int   g_total;
__device__ __align__(8) int2 g_edge[EE];   // .x = src, .y = float bits of dinv[src]

// ---------------------------------------------------------------------------
// bf16 split: x = hi + lo (both bf16); packs (x,y) pairs into u32 (x=low half)
// ---------------------------------------------------------------------------
__device__ __forceinline__ void split2(float x, float y, uint32_t& hi, uint32_t& lo) {
    __nv_bfloat162 h = __floats2bfloat162_rn(x, y);
    float hx = __bfloat162float(__low2bfloat16(h));
    float hy = __bfloat162float(__high2bfloat16(h));
    __nv_bfloat162 l = __floats2bfloat162_rn(x - hx, y - hy);
    hi = *reinterpret_cast<uint32_t*>(&h);
    lo = *reinterpret_cast<uint32_t*>(&l);
}

// mma.sync m16n8k16 row.col bf16 -> f32 accumulate
__device__ __forceinline__ void mma16816(float* c, const uint32_t* a, const uint32_t* b) {
    asm volatile(
        "mma.sync.aligned.m16n8k16.row.col.f32.bf16.bf16.f32 "
        "{%0,%1,%2,%3}, {%4,%5,%6,%7}, {%8,%9}, {%0,%1,%2,%3};"
        : "+f"(c[0]), "+f"(c[1]), "+f"(c[2]), "+f"(c[3])
        : "r"(a[0]), "r"(a[1]), "r"(a[2]), "r"(a[3]),
          "r"(b[0]), "r"(b[1]));
}

// Fragment-order SMEM index math (u32 units), p = k/2 local to a 64-k chunk.
__device__ __forceinline__ int a_idx(int r, int p) {
    int s = p >> 3, q = p & 7;
    return (((s << 3) | (r >> 4)) << 7)
         + ((((r & 7) << 2) | (q & 3)) << 2)
         + (((q >> 2) << 1) | ((r >> 3) & 1));
}
__device__ __forceinline__ int b_idx(int n, int p) {
    int s = p >> 3, q = p & 7;
    return (((s << 4) | (n >> 3)) << 6)
         + ((((n & 7) << 2) | (q & 3)) << 1)
         + (q >> 2);
}

// ---------------------------------------------------------------------------
// Graph preprocessing
// ---------------------------------------------------------------------------
__global__ void k_zero_deg() {
    int i = blockIdx.x * blockDim.x + threadIdx.x;
    if (i < NN) g_deg[i] = 0;
    if (i == 0) g_total = 0;
}
__global__ void k_deg(const int* __restrict__ ei) {
    int e = blockIdx.x * blockDim.x + threadIdx.x;
    if (e < EE) atomicAdd(&g_deg[ei[EE + e]], 1);
}
// fused dinv + unordered-CSR segment allocation
__global__ void k_dinvrow() {
    int i = blockIdx.x * blockDim.x + threadIdx.x;
    if (i < NN) {
        int d = g_deg[i];
        g_dinv[i] = rsqrtf((float)(d + 1));
        int beg = atomicAdd(&g_total, d);
        g_rowptr[i] = beg;
        g_cursor[i] = beg;
    }
}
__global__ void k_fill(const int* __restrict__ ei) {
    int e = blockIdx.x * blockDim.x + threadIdx.x;
    if (e >= EE) return;
    int s = ei[e];
    int d = ei[EE + e];
    int pos = atomicAdd(&g_cursor[d], 1);
    g_edge[pos] = make_int2(s, __float_as_int(g_dinv[s]));
}

// Convert weight W[K,128] (k-major) to n-major bf16 pair arrays [n][Kp].
__global__ void k_convW(const float* __restrict__ W, uint32_t* __restrict__ hi,
                        uint32_t* __restrict__ lo, int Kpairs) {
    int p = blockIdx.x;     // pair index
    int n = threadIdx.x;    // col
    float a = W[(size_t)(2 * p) * 128 + n];
    float b = W[(size_t)(2 * p + 1) * 128 + n];
    uint32_t h, l;
    split2(a, b, h, l);
    hi[n * Kpairs + p] = h;
    lo[n * Kpairs + p] = l;
}

// ---------------------------------------------------------------------------
// bf16x3 HMMA GEMM: C[M x 128] = A[M x K] @ B^T, B pre-split n-major pairs.
// AMODE 0: A fp32 row-major (split in-kernel); AMODE 1: A pre-split pairs [row][K/2]
// OUTH: write __half wire; else fp32 (+EPI==1: (v+1)*0.5)
// ---------------------------------------------------------------------------
#define HG_SMEM 65536

template<int AMODE, bool OUTH, int EPI>
__global__ __launch_bounds__(256, 1)
void k_hgemm(const float* __restrict__ Af,
             const uint32_t* __restrict__ APhi, const uint32_t* __restrict__ APlo,
             const uint32_t* __restrict__ Bhi_g, const uint32_t* __restrict__ Blo_g,
             float* __restrict__ Cf, __half* __restrict__ Ch, int M, int K)
{
    extern __shared__ __align__(16) uint32_t smem[];
    uint32_t* sAhi = smem;
    uint32_t* sAlo = smem + 4096;
    uint32_t* sBhi = smem + 8192;
    uint32_t* sBlo = smem + 12288;

    int tid = threadIdx.x;
    int wid = tid >> 5, lane = tid & 31;
    int wm = wid & 3;          // warp row (32 rows each)
    int wn = wid >> 2;         // warp col (64 cols each)
    int row0 = blockIdx.x * 128;
    int Kp = K >> 1;

    float acc[2][8][4];
    #pragma unroll
    for (int a = 0; a < 2; a++)
        #pragma unroll
        for (int b = 0; b < 8; b++)
            #pragma unroll
            for (int c = 0; c < 4; c++) acc[a][b][c] = 0.f;

    int nchunks = K >> 6;
    for (int ch = 0; ch < nchunks; ch++) {
        // ---- A chunk ----
        if (AMODE == 0) {
            int r = tid >> 1;
            int k4b = (tid & 1) * 8;
            const float* arow = Af + (size_t)(row0 + r) * K + (ch << 6);
            bool valid = (row0 + r) < M;
            #pragma unroll
            for (int i = 0; i < 8; i++) {
                int k = (k4b + i) * 4;
                float4 v = make_float4(0.f, 0.f, 0.f, 0.f);
                if (valid) v = *(const float4*)(arow + k);
                uint32_t h0, l0, h1, l1;
                split2(v.x, v.y, h0, l0);
                split2(v.z, v.w, h1, l1);
                int p = k >> 1;
                int i0 = a_idx(r, p), i1 = a_idx(r, p + 1);
                sAhi[i0] = h0; sAlo[i0] = l0;
                sAhi[i1] = h1; sAlo[i1] = l1;
            }
        } else {
            int r = tid >> 1, seg = tid & 1;
            bool valid = (row0 + r) < M;
            const uint32_t* ah = APhi + (size_t)(row0 + r) * Kp + ch * 32 + seg * 16;
            const uint32_t* al = APlo + (size_t)(row0 + r) * Kp + ch * 32 + seg * 16;
            #pragma unroll
            for (int i = 0; i < 4; i++) {
                uint4 vh = make_uint4(0, 0, 0, 0), vl = make_uint4(0, 0, 0, 0);
                if (valid) { vh = *(const uint4*)(ah + i * 4); vl = *(const uint4*)(al + i * 4); }
                int pb = seg * 16 + i * 4;
                int i0 = a_idx(r, pb + 0), i1 = a_idx(r, pb + 1);
                int i2 = a_idx(r, pb + 2), i3 = a_idx(r, pb + 3);
                sAhi[i0] = vh.x; sAlo[i0] = vl.x;
                sAhi[i1] = vh.y; sAlo[i1] = vl.y;
                sAhi[i2] = vh.z; sAlo[i2] = vl.z;
                sAhi[i3] = vh.w; sAlo[i3] = vl.w;
            }
        }
        // ---- B chunk: pre-split n-major [n][Kp] ----
        {
            int n = tid >> 1, seg = tid & 1;
            const uint32_t* bh = Bhi_g + (size_t)n * Kp + ch * 32 + seg * 16;
            const uint32_t* bl = Blo_g + (size_t)n * Kp + ch * 32 + seg * 16;
            #pragma unroll
            for (int i = 0; i < 4; i++) {
                uint4 vh = *(const uint4*)(bh + i * 4);
                uint4 vl = *(const uint4*)(bl + i * 4);
                int pb = seg * 16 + i * 4;
                int i0 = b_idx(n, pb + 0), i1 = b_idx(n, pb + 1);
                int i2 = b_idx(n, pb + 2), i3 = b_idx(n, pb + 3);
                sBhi[i0] = vh.x; sBlo[i0] = vl.x;
                sBhi[i1] = vh.y; sBlo[i1] = vl.y;
                sBhi[i2] = vh.z; sBlo[i2] = vl.z;
                sBhi[i3] = vh.w; sBlo[i3] = vl.w;
            }
        }
        __syncthreads();

        // ---- MMA mainloop: 4 k16-steps ----
        #pragma unroll
        for (int s = 0; s < 4; s++) {
            uint4 ah0 = *(const uint4*)(sAhi + (((s << 3) | (wm * 2 + 0)) << 7) + (lane << 2));
            uint4 ah1 = *(const uint4*)(sAhi + (((s << 3) | (wm * 2 + 1)) << 7) + (lane << 2));
            uint4 al0 = *(const uint4*)(sAlo + (((s << 3) | (wm * 2 + 0)) << 7) + (lane << 2));
            uint4 al1 = *(const uint4*)(sAlo + (((s << 3) | (wm * 2 + 1)) << 7) + (lane << 2));
            #pragma unroll
            for (int j = 0; j < 8; j++) {
                int nt = wn * 8 + j;
                uint2 bh = *(const uint2*)(sBhi + (((s << 4) | nt) << 6) + (lane << 1));
                uint2 bl = *(const uint2*)(sBlo + (((s << 4) | nt) << 6) + (lane << 1));
                mma16816(acc[0][j], (const uint32_t*)&ah0, (const uint32_t*)&bh);
                mma16816(acc[0][j], (const uint32_t*)&ah0, (const uint32_t*)&bl);
                mma16816(acc[0][j], (const uint32_t*)&al0, (const uint32_t*)&bh);
                mma16816(acc[1][j], (const uint32_t*)&ah1, (const uint32_t*)&bh);
                mma16816(acc[1][j], (const uint32_t*)&ah1, (const uint32_t*)&bl);
                mma16816(acc[1][j], (const uint32_t*)&al1, (const uint32_t*)&bh);
            }
        }
        __syncthreads();
    }

    // ---- epilogue ----
    int rbase = row0 + wm * 32 + (lane >> 2);
    int cbase = wn * 64 + (lane & 3) * 2;
    #pragma unroll
    for (int mt = 0; mt < 2; mt++) {
        #pragma unroll
        for (int j = 0; j < 8; j++) {
            int rr = rbase + mt * 16;
            int cc = cbase + j * 8;
            if (OUTH) {
                __half2 v0 = __floats2half2_rn(acc[mt][j][0], acc[mt][j][1]);
                __half2 v1 = __floats2half2_rn(acc[mt][j][2], acc[mt][j][3]);
                if (rr < M)     *(__half2*)(Ch + (size_t)rr * 128 + cc) = v0;
                if (rr + 8 < M) *(__half2*)(Ch + (size_t)(rr + 8) * 128 + cc) = v1;
            } else {
                float2 v0 = make_float2(acc[mt][j][0], acc[mt][j][1]);
                float2 v1 = make_float2(acc[mt][j][2], acc[mt][j][3]);
                if (EPI == 1) {
                    v0.x = (v0.x + 1.f) * 0.5f; v0.y = (v0.y + 1.f) * 0.5f;
                    v1.x = (v1.x + 1.f) * 0.5f; v1.y = (v1.y + 1.f) * 0.5f;
                }
                if (rr < M)     *(float2*)(Cf + (size_t)rr * 128 + cc) = v0;
                if (rr + 8 < M) *(float2*)(Cf + (size_t)(rr + 8) * 128 + cc) = v1;
            }
        }
    }
}

// ---------------------------------------------------------------------------
// CSR aggregation over fp16 wire, 4-wide MLP batching.
// OUT=0: relu -> bf16 pair arrays (next GEMM A)
// OUT=1: FUSED L2 rownorm -> g_A fp32 + bf16 pair arrays
// ---------------------------------------------------------------------------
__device__ __forceinline__ void agg_step(float4& acc, const __half* h,
                                         int2 ed, float di, int lane) {
    float w = __int_as_float(ed.y) * di;
    uint2 xv = *(const uint2*)(h + (size_t)ed.x * 128 + lane * 4);
    float2 x01 = __half22float2(*reinterpret_cast<__half2*>(&xv.x));
    float2 x23 = __half22float2(*reinterpret_cast<__half2*>(&xv.y));
    acc.x += w * x01.x; acc.y += w * x01.y;
    acc.z += w * x23.x; acc.w += w * x23.y;
}

template<int OUT>
__global__ void k_agg(const __half* __restrict__ h, const float* __restrict__ bias)
{
    int warp = threadIdx.x >> 5, lane = threadIdx.x & 31;
    int node = blockIdx.x * 8 + warp;
    if (node >= NN) return;

    float di = g_dinv[node];
    float4 b = *(const float4*)(bias + lane * 4);
    uint2 hv = *(const uint2*)(h + (size_t)node * 128 + lane * 4);
    float2 s01 = __half22float2(*reinterpret_cast<__half2*>(&hv.x));
    float2 s23 = __half22float2(*reinterpret_cast<__half2*>(&hv.y));
    float w0 = di * di;
    float4 acc = make_float4(b.x + w0 * s01.x, b.y + w0 * s01.y,
                             b.z + w0 * s23.x, b.w + w0 * s23.y);

    int e = g_rowptr[node], end = g_cursor[node];
    for (; e + 4 <= end; e += 4) {
        int2 e0 = g_edge[e + 0];
        int2 e1 = g_edge[e + 1];
        int2 e2 = g_edge[e + 2];
        int2 e3 = g_edge[e + 3];
        agg_step(acc, h, e0, di, lane);
        agg_step(acc, h, e1, di, lane);
        agg_step(acc, h, e2, di, lane);
        agg_step(acc, h, e3, di, lane);
    }
    for (; e < end; e++) agg_step(acc, h, g_edge[e], di, lane);

    if (OUT == 0) {
        acc.x = fmaxf(acc.x, 0.f); acc.y = fmaxf(acc.y, 0.f);
        acc.z = fmaxf(acc.z, 0.f); acc.w = fmaxf(acc.w, 0.f);
    } else {
        // fused L2 row-normalize
        float s = acc.x * acc.x + acc.y * acc.y + acc.z * acc.z + acc.w * acc.w;
        #pragma unroll
        for (int off = 16; off; off >>= 1) s += __shfl_xor_sync(~0u, s, off);
        float inv = 1.0f / sqrtf(s);
        acc.x *= inv; acc.y *= inv; acc.z *= inv; acc.w *= inv;
        *(float4*)(g_A + (size_t)node * 128 + lane * 4) = acc;
    }
    uint32_t h0, l0, h1, l1;
    split2(acc.x, acc.y, h0, l0);
    split2(acc.z, acc.w, h1, l1);
    *(uint2*)(g_Phi + (size_t)node * 64 + lane * 2) = make_uint2(h0, h1);
    *(uint2*)(g_Plo + (size_t)node * 64 + lane * 2) = make_uint2(l0, l1);
}

__global__ void k_anchors(const int* __restrict__ prot) {
    int p = blockIdx.x, t = threadIdx.x;   // 128 threads
    int src = prot[p];
    g_anchors[p * HD + t] = g_A[(size_t)src * HD + t];
    if (t < 64) {
        g_AncHi[p * 64 + t] = g_Phi[(size_t)src * 64 + t];
        g_AncLo[p * 64 + t] = g_Plo[(size_t)src * 64 + t];
    }
}

__global__ void k_proto_hp(const float* __restrict__ lw1, const float* __restrict__ lb1) {
    __shared__ float a[HD];
    int p = blockIdx.x, j = threadIdx.x;
    a[j] = g_anchors[p * HD + j];
    __syncthreads();
    float acc = lb1[j];
    #pragma unroll 8
    for (int k = 0; k < HD; k++) acc += a[k] * lw1[k * HD + j];
    g_hp[p * HD + j] = fmaxf(acc, 0.f);
}

__global__ void k_proto_out(const float* __restrict__ lw2, const float* __restrict__ lb2,
                            float* __restrict__ op)
{
    __shared__ float h[HD];
    __shared__ float lg[CC];
    __shared__ float red[2];
    int p = blockIdx.x, t = threadIdx.x;   // 64 threads
    h[t] = g_hp[p * HD + t];
    h[t + 64] = g_hp[p * HD + 64 + t];
    __syncthreads();
    if (t < CC) {
        float acc = lb2[t];
        #pragma unroll 8
        for (int j = 0; j < HD; j++) acc += h[j] * lw2[j * CC + t];
        lg[t] = acc;
    }
    __syncthreads();
    if (t == 0) {
        float m = -1e30f;
        for (int c = 0; c < CC; c++) m = fmaxf(m, lg[c]);
        float s = 0.f;
        for (int c = 0; c < CC; c++) s += expf(lg[c] - m);
        red[0] = m; red[1] = logf(s);
    }
    __syncthreads();
    if (t < CC) op[p * CC + t] = lg[t] - red[0] - red[1];
}

__global__ void k_out(const float* __restrict__ xrel, const float* __restrict__ proto,
                      float* __restrict__ out)
{
    __shared__ float sp[PP * CC];
    __shared__ float srow[8][PP];
    int tid = threadIdx.x;
    for (int i = tid; i < PP * CC; i += 256) sp[i] = proto[i];
    int warp = tid >> 5, lane = tid & 31;
    int node = blockIdx.x * 8 + warp;
    if (node < NN) {
        float4 v = *(const float4*)(xrel + (size_t)node * PP + lane * 4);
        *(float4*)&srow[warp][lane * 4] = v;
    }
    __syncthreads();
    if (node >= NN) return;

    const float* r = srow[warp];
    int c2 = 32 + (lane & 7);
    float a0 = 0.f, a1 = 0.f;
    #pragma unroll 8
    for (int p = 0; p < PP; p++) {
        float x = r[p];
        a0 += x * sp[p * CC + lane];
        a1 += x * sp[p * CC + c2];
    }
    float m = a0;
    if (lane < 8) m = fmaxf(m, a1);
    #pragma unroll
    for (int off = 16; off; off >>= 1) m = fmaxf(m, __shfl_xor_sync(~0u, m, off));
    float se = expf(a0 - m) + ((lane < 8) ? expf(a1 - m) : 0.f);
    #pragma unroll
    for (int off = 16; off; off >>= 1) se += __shfl_xor_sync(~0u, se, off);
    float lse = m + logf(se);
    out[(size_t)node * CC + lane] = a0 - lse;
    if (lane < 8) out[(size_t)node * CC + 32 + lane] = a1 - lse;
}

// ---------------------------------------------------------------------------
// launch
// ---------------------------------------------------------------------------
extern "C" void kernel_launch(void* const* d_in, const int* in_sizes, int n_in,
                              void* d_out, int out_size)
{
    const float* x    = (const float*)d_in[0];
    const int*   ei   = (const int*)  d_in[1];
    const int*   prot = (const int*)  d_in[2];
    const float* W0   = (const float*)d_in[3];
    const float* b0   = (const float*)d_in[4];
    const float* Wh   = (const float*)d_in[5];
    const float* bh   = (const float*)d_in[6];
    const float* lw1  = (const float*)d_in[7];
    const float* lb1  = (const float*)d_in[8];
    const float* lw2  = (const float*)d_in[9];
    const float* lb2  = (const float*)d_in[10];

    float* out   = (float*)d_out;                      // [N, C]
    float* xrel  = out + (size_t)NN * CC;              // [N, P]
    float* oprot = xrel + (size_t)NN * PP;             // [P, C]

    __half* pH;
    uint32_t *pPhi, *pPlo, *pW0h, *pW0l, *pW1h, *pW1l, *pW2h, *pW2l, *pAnH, *pAnL;
    cudaGetSymbolAddress((void**)&pH, g_H);
    cudaGetSymbolAddress((void**)&pPhi, g_Phi);
    cudaGetSymbolAddress((void**)&pPlo, g_Plo);
    cudaGetSymbolAddress((void**)&pW0h, g_W0hi);
    cudaGetSymbolAddress((void**)&pW0l, g_W0lo);
    cudaGetSymbolAddress((void**)&pW1h, g_W1hi);
    cudaGetSymbolAddress((void**)&pW1l, g_W1lo);
    cudaGetSymbolAddress((void**)&pW2h, g_W2hi);
    cudaGetSymbolAddress((void**)&pW2l, g_W2lo);
    cudaGetSymbolAddress((void**)&pAnH, g_AncHi);
    cudaGetSymbolAddress((void**)&pAnL, g_AncLo);

    cudaFuncSetAttribute(k_hgemm<0, true, 0>,
                         cudaFuncAttributeMaxDynamicSharedMemorySize, HG_SMEM);
    cudaFuncSetAttribute(k_hgemm<1, true, 0>,
                         cudaFuncAttributeMaxDynamicSharedMemorySize, HG_SMEM);
    cudaFuncSetAttribute(k_hgemm<1, false, 1>,
                         cudaFuncAttributeMaxDynamicSharedMemorySize, HG_SMEM);

    const int TB = 256;
    dim3 gN((NN + TB - 1) / TB);
    dim3 gE((EE + TB - 1) / TB);
    dim3 gGemm((NN + 127) / 128);
    dim3 gWarp8((NN + 7) / 8);

    // Launch order arranged so ncu (-s 5 -c 1) captures launch #6 = layer-0 GEMM.
    // (1-3) weight conversion, (4-5) deg prep — all independent of the GEMM.
    k_convW<<<128, 128>>>(W0, pW0h, pW0l, 128);              // 1
    k_convW<<<64, 128>>>(Wh, pW1h, pW1l, 64);                // 2
    k_convW<<<64, 128>>>(Wh + HD * HD, pW2h, pW2l, 64);      // 3
    k_zero_deg<<<gN, TB>>>();                                // 4
    k_deg<<<gE, TB>>>(ei);                                   // 5

    // --- layer 0 GEMM: h = x @ W0 (fp16 wire) --- (6: profiled)
    k_hgemm<0, true, 0><<<gGemm, 256, HG_SMEM>>>(x, nullptr, nullptr, pW0h, pW0l,
                                                 nullptr, pH, NN, FIN);

    // --- rest of graph preprocessing ---
    k_dinvrow<<<gN, TB>>>();                                 // 7
    k_fill<<<gE, TB>>>(ei);                                  // 8

    // --- layer 0 aggregate -> relu -> bf16 pairs ---
    k_agg<0><<<gWarp8, 256>>>(pH, b0);

    // --- layer 1 ---
    k_hgemm<1, true, 0><<<gGemm, 256, HG_SMEM>>>(nullptr, pPhi, pPlo, pW1h, pW1l,
                                                 nullptr, pH, NN, HD);
    k_agg<0><<<gWarp8, 256>>>(pH, bh);

    // --- layer 2 (agg fused with L2 rownorm) ---
    k_hgemm<1, true, 0><<<gGemm, 256, HG_SMEM>>>(nullptr, pPhi, pPlo, pW2h, pW2l,
                                                 nullptr, pH, NN, HD);
    k_agg<1><<<gWarp8, 256>>>(pH, bh + HD);

    // --- anchors (fp32 + pairs), proto head ---
    k_anchors<<<PP, HD>>>(prot);
    k_proto_hp<<<PP, HD>>>(lw1, lb1);
    k_proto_out<<<PP, 64>>>(lw2, lb2, oprot);

    // --- x_rel = (hn @ anchors^T + 1) * 0.5 ---
    k_hgemm<1, false, 1><<<gGemm, 256, HG_SMEM>>>(nullptr, pPhi, pPlo, pAnH, pAnL,
                                                  xrel, nullptr, NN, HD);

    // --- out = log_softmax(x_rel @ out_proto) ---
    k_out<<<gWarp8, 256>>>(xrel, oprot, out);
}

// round 9
// speedup vs baseline: 1.5793x; 1.1099x over previous
#include <cuda_runtime.h>
#include <cuda_bf16.h>
#include <cuda_fp16.h>
#include <math.h>
#include <stdint.h>

// Problem constants (fixed by the reference)
#define NN   50000      // nodes
#define EE   1600000    // edges
#define FIN  256
#define HD   128        // hidden
#define CC   40         // classes
#define PP   128        // prototypes

// ---------------------------------------------------------------------------
// Scratch (static device globals; no allocation in kernel_launch)
// ---------------------------------------------------------------------------
__device__ __align__(16) __half   g_H[(size_t)NN * 128];    // fp16 wire A
__device__ __align__(16) __half   g_H2[(size_t)NN * 128];   // fp16 wire B
__device__ __align__(16) float    g_A[(size_t)NN * 128];    // hn fp32
__device__ __align__(16) uint32_t g_W0hi[128 * 128], g_W0lo[128 * 128];
__device__ __align__(16) uint32_t g_W1hi[128 * 64],  g_W1lo[128 * 64];
__device__ __align__(16) uint32_t g_W2hi[128 * 64],  g_W2lo[128 * 64];
__device__ __align__(16) uint32_t g_AncHi[128 * 64], g_AncLo[128 * 64];
__device__ __align__(16) float    g_anchors[PP * HD];
__device__ __align__(16) float    g_hp[PP * HD];
__device__ int   g_deg[NN];
__device__ float g_dinv[NN];
__device__ int   g_rowptr[NN];
__device__ int   g_cursor[NN];
__device__ int   g_total;
__device__ __align__(8) int2 g_edge[EE];   // .x = src, .y = float bits of dinv[src]

// ---------------------------------------------------------------------------
// fp16 split: x = hi + lo (both fp16); packs (x,y) pairs into u32 (x=low half)
// ---------------------------------------------------------------------------
__device__ __forceinline__ void hsplit2(float x, float y, uint32_t& hi, uint32_t& lo) {
    __half2 h = __floats2half2_rn(x, y);
    float2 hf = __half22float2(h);
    __half2 l = __floats2half2_rn(x - hf.x, y - hf.y);
    hi = *reinterpret_cast<uint32_t*>(&h);
    lo = *reinterpret_cast<uint32_t*>(&l);
}

// mma.sync m16n8k16 row.col fp16 -> f32 accumulate
__device__ __forceinline__ void mma16816(float* c, const uint32_t* a, const uint32_t* b) {
    asm volatile(
        "mma.sync.aligned.m16n8k16.row.col.f32.f16.f16.f32 "
        "{%0,%1,%2,%3}, {%4,%5,%6,%7}, {%8,%9}, {%0,%1,%2,%3};"
        : "+f"(c[0]), "+f"(c[1]), "+f"(c[2]), "+f"(c[3])
        : "r"(a[0]), "r"(a[1]), "r"(a[2]), "r"(a[3]),
          "r"(b[0]), "r"(b[1]));
}

// Fragment-order SMEM index math (u32 = fp16 pair along k), p = k/2 in 64-k chunk.
__device__ __forceinline__ int a_idx(int r, int p) {
    int s = p >> 3, q = p & 7;
    return (((s << 3) | (r >> 4)) << 7)
         + ((((r & 7) << 2) | (q & 3)) << 2)
         + (((q >> 2) << 1) | ((r >> 3) & 1));
}
__device__ __forceinline__ int b_idx(int n, int p) {
    int s = p >> 3, q = p & 7;
    return (((s << 4) | (n >> 3)) << 6)
         + ((((n & 7) << 2) | (q & 3)) << 1)
         + (q >> 2);
}

// ---------------------------------------------------------------------------
// Graph preprocessing
// ---------------------------------------------------------------------------
__global__ void k_zero_deg() {
    int i = blockIdx.x * blockDim.x + threadIdx.x;
    if (i < NN) g_deg[i] = 0;
    if (i == 0) g_total = 0;
}
__global__ void k_deg(const int* __restrict__ ei) {
    int e = blockIdx.x * blockDim.x + threadIdx.x;
    if (e < EE) atomicAdd(&g_deg[ei[EE + e]], 1);
}
__global__ void k_dinvrow() {
    int i = blockIdx.x * blockDim.x + threadIdx.x;
    if (i < NN) {
        int d = g_deg[i];
        g_dinv[i] = rsqrtf((float)(d + 1));
        int beg = atomicAdd(&g_total, d);
        g_rowptr[i] = beg;
        g_cursor[i] = beg;
    }
}
__global__ void k_fill(const int* __restrict__ ei) {
    int e = blockIdx.x * blockDim.x + threadIdx.x;
    if (e >= EE) return;
    int s = ei[e];
    int d = ei[EE + e];
    int pos = atomicAdd(&g_cursor[d], 1);
    g_edge[pos] = make_int2(s, __float_as_int(g_dinv[s]));
}

// Convert weight W[K,128] (k-major) to n-major fp16 hi/lo pair arrays [n][Kp].
__global__ void k_convW(const float* __restrict__ W, uint32_t* __restrict__ hi,
                        uint32_t* __restrict__ lo, int Kpairs) {
    int p = blockIdx.x;     // k-pair index
    int n = threadIdx.x;    // col
    float a = W[(size_t)(2 * p) * 128 + n];
    float b = W[(size_t)(2 * p + 1) * 128 + n];
    uint32_t h, l;
    hsplit2(a, b, h, l);
    hi[n * Kpairs + p] = h;
    lo[n * Kpairs + p] = l;
}

// ---------------------------------------------------------------------------
// fp16x2 HMMA GEMM: C[M x 128] = A[M x K] @ B^T
//   A: fp16 single (AMODE 0: fp32 source converted in-kernel; AMODE 1: fp16 rows)
//   B: pre-split fp16 hi/lo n-major pair arrays  ->  D = A*Bhi + A*Blo
// OUTH: write __half wire; else fp32 (+EPI==1: (v+1)*0.5)
// SMEM (u32): sA[4096] sBhi[4096] sBlo[4096] = 48KB
// ---------------------------------------------------------------------------
#define HG_SMEM 49152

template<int AMODE, bool OUTH, int EPI>
__global__ __launch_bounds__(256, 1)
void k_hgemm(const float* __restrict__ Af, const __half* __restrict__ Ah,
             const uint32_t* __restrict__ Bhi_g, const uint32_t* __restrict__ Blo_g,
             float* __restrict__ Cf, __half* __restrict__ Ch, int M, int K)
{
    extern __shared__ __align__(16) uint32_t smem[];
    uint32_t* sA   = smem;
    uint32_t* sBhi = smem + 4096;
    uint32_t* sBlo = smem + 8192;

    int tid = threadIdx.x;
    int wid = tid >> 5, lane = tid & 31;
    int wm = wid & 3;          // warp row (32 rows each)
    int wn = wid >> 2;         // warp col (64 cols each)
    int row0 = blockIdx.x * 128;
    int Kp = K >> 1;

    float acc[2][8][4];
    #pragma unroll
    for (int a = 0; a < 2; a++)
        #pragma unroll
        for (int b = 0; b < 8; b++)
            #pragma unroll
            for (int c = 0; c < 4; c++) acc[a][b][c] = 0.f;

    int nchunks = K >> 6;
    for (int ch = 0; ch < nchunks; ch++) {
        int r = tid >> 1, seg = tid & 1;
        bool valid = (row0 + r) < M;
        // ---- A chunk: 128 rows x 64 k as fp16 pairs ----
        if (AMODE == 0) {
            const float* arow = Af + (size_t)(row0 + r) * K + (ch << 6) + seg * 32;
            #pragma unroll
            for (int i = 0; i < 4; i++) {
                float4 v0 = make_float4(0.f, 0.f, 0.f, 0.f);
                float4 v1 = make_float4(0.f, 0.f, 0.f, 0.f);
                if (valid) {
                    v0 = *(const float4*)(arow + i * 8);
                    v1 = *(const float4*)(arow + i * 8 + 4);
                }
                uint32_t p0, p1, p2, p3;
                {
                    __half2 h0 = __floats2half2_rn(v0.x, v0.y);
                    __half2 h1 = __floats2half2_rn(v0.z, v0.w);
                    __half2 h2 = __floats2half2_rn(v1.x, v1.y);
                    __half2 h3 = __floats2half2_rn(v1.z, v1.w);
                    p0 = *reinterpret_cast<uint32_t*>(&h0);
                    p1 = *reinterpret_cast<uint32_t*>(&h1);
                    p2 = *reinterpret_cast<uint32_t*>(&h2);
                    p3 = *reinterpret_cast<uint32_t*>(&h3);
                }
                int pb = seg * 16 + i * 4;
                sA[a_idx(r, pb + 0)] = p0;
                sA[a_idx(r, pb + 1)] = p1;
                sA[a_idx(r, pb + 2)] = p2;
                sA[a_idx(r, pb + 3)] = p3;
            }
        } else {
            const uint32_t* arow = (const uint32_t*)(Ah + (size_t)(row0 + r) * 128)
                                   + ch * 32 + seg * 16;
            #pragma unroll
            for (int i = 0; i < 4; i++) {
                uint4 v = make_uint4(0, 0, 0, 0);
                if (valid) v = *(const uint4*)(arow + i * 4);
                int pb = seg * 16 + i * 4;
                sA[a_idx(r, pb + 0)] = v.x;
                sA[a_idx(r, pb + 1)] = v.y;
                sA[a_idx(r, pb + 2)] = v.z;
                sA[a_idx(r, pb + 3)] = v.w;
            }
        }
        // ---- B chunk: pre-split n-major [n][Kp] ----
        {
            int n = tid >> 1;
            const uint32_t* bh = Bhi_g + (size_t)n * Kp + ch * 32 + seg * 16;
            const uint32_t* bl = Blo_g + (size_t)n * Kp + ch * 32 + seg * 16;
            #pragma unroll
            for (int i = 0; i < 4; i++) {
                uint4 vh = *(const uint4*)(bh + i * 4);
                uint4 vl = *(const uint4*)(bl + i * 4);
                int pb = seg * 16 + i * 4;
                int i0 = b_idx(n, pb + 0), i1 = b_idx(n, pb + 1);
                int i2 = b_idx(n, pb + 2), i3 = b_idx(n, pb + 3);
                sBhi[i0] = vh.x; sBlo[i0] = vl.x;
                sBhi[i1] = vh.y; sBlo[i1] = vl.y;
                sBhi[i2] = vh.z; sBlo[i2] = vl.z;
                sBhi[i3] = vh.w; sBlo[i3] = vl.w;
            }
        }
        __syncthreads();

        // ---- MMA mainloop: 4 k16-steps, 2 MMAs per fragment pair ----
        #pragma unroll
        for (int s = 0; s < 4; s++) {
            uint4 a0 = *(const uint4*)(sA + (((s << 3) | (wm * 2 + 0)) << 7) + (lane << 2));
            uint4 a1 = *(const uint4*)(sA + (((s << 3) | (wm * 2 + 1)) << 7) + (lane << 2));
            #pragma unroll
            for (int j = 0; j < 8; j++) {
                int nt = wn * 8 + j;
                uint2 bh = *(const uint2*)(sBhi + (((s << 4) | nt) << 6) + (lane << 1));
                uint2 bl = *(const uint2*)(sBlo + (((s << 4) | nt) << 6) + (lane << 1));
                mma16816(acc[0][j], (const uint32_t*)&a0, (const uint32_t*)&bh);
                mma16816(acc[0][j], (const uint32_t*)&a0, (const uint32_t*)&bl);
                mma16816(acc[1][j], (const uint32_t*)&a1, (const uint32_t*)&bh);
                mma16816(acc[1][j], (const uint32_t*)&a1, (const uint32_t*)&bl);
            }
        }
        __syncthreads();
    }

    // ---- epilogue ----
    int rbase = row0 + wm * 32 + (lane >> 2);
    int cbase = wn * 64 + (lane & 3) * 2;
    #pragma unroll
    for (int mt = 0; mt < 2; mt++) {
        #pragma unroll
        for (int j = 0; j < 8; j++) {
            int rr = rbase + mt * 16;
            int cc = cbase + j * 8;
            if (OUTH) {
                __half2 v0 = __floats2half2_rn(acc[mt][j][0], acc[mt][j][1]);
                __half2 v1 = __floats2half2_rn(acc[mt][j][2], acc[mt][j][3]);
                if (rr < M)     *(__half2*)(Ch + (size_t)rr * 128 + cc) = v0;
                if (rr + 8 < M) *(__half2*)(Ch + (size_t)(rr + 8) * 128 + cc) = v1;
            } else {
                float2 v0 = make_float2(acc[mt][j][0], acc[mt][j][1]);
                float2 v1 = make_float2(acc[mt][j][2], acc[mt][j][3]);
                if (EPI == 1) {
                    v0.x = (v0.x + 1.f) * 0.5f; v0.y = (v0.y + 1.f) * 0.5f;
                    v1.x = (v1.x + 1.f) * 0.5f; v1.y = (v1.y + 1.f) * 0.5f;
                }
                if (rr < M)     *(float2*)(Cf + (size_t)rr * 128 + cc) = v0;
                if (rr + 8 < M) *(float2*)(Cf + (size_t)(rr + 8) * 128 + cc) = v1;
            }
        }
    }
}

// ---------------------------------------------------------------------------
// CSR aggregation over fp16 wire, 4-wide MLP batching.
// OUT=0: relu -> fp16 out wire
// OUT=1: FUSED L2 rownorm -> g_A fp32 + fp16 out wire (hn)
// ---------------------------------------------------------------------------
__device__ __forceinline__ void agg_step(float4& acc, const __half* h,
                                         int2 ed, float di, int lane) {
    float w = __int_as_float(ed.y) * di;
    uint2 xv = *(const uint2*)(h + (size_t)ed.x * 128 + lane * 4);
    float2 x01 = __half22float2(*reinterpret_cast<__half2*>(&xv.x));
    float2 x23 = __half22float2(*reinterpret_cast<__half2*>(&xv.y));
    acc.x += w * x01.x; acc.y += w * x01.y;
    acc.z += w * x23.x; acc.w += w * x23.y;
}

template<int OUT>
__global__ void k_agg(const __half* __restrict__ h, __half* __restrict__ o,
                      const float* __restrict__ bias)
{
    int warp = threadIdx.x >> 5, lane = threadIdx.x & 31;
    int node = blockIdx.x * 8 + warp;
    if (node >= NN) return;

    float di = g_dinv[node];
    float4 b = *(const float4*)(bias + lane * 4);
    uint2 hv = *(const uint2*)(h + (size_t)node * 128 + lane * 4);
    float2 s01 = __half22float2(*reinterpret_cast<__half2*>(&hv.x));
    float2 s23 = __half22float2(*reinterpret_cast<__half2*>(&hv.y));
    float w0 = di * di;
    float4 acc = make_float4(b.x + w0 * s01.x, b.y + w0 * s01.y,
                             b.z + w0 * s23.x, b.w + w0 * s23.y);

    int e = g_rowptr[node], end = g_cursor[node];
    for (; e + 4 <= end; e += 4) {
        int2 e0 = g_edge[e + 0];
        int2 e1 = g_edge[e + 1];
        int2 e2 = g_edge[e + 2];
        int2 e3 = g_edge[e + 3];
        agg_step(acc, h, e0, di, lane);
        agg_step(acc, h, e1, di, lane);
        agg_step(acc, h, e2, di, lane);
        agg_step(acc, h, e3, di, lane);
    }
    for (; e < end; e++) agg_step(acc, h, g_edge[e], di, lane);

    if (OUT == 0) {
        acc.x = fmaxf(acc.x, 0.f); acc.y = fmaxf(acc.y, 0.f);
        acc.z = fmaxf(acc.z, 0.f); acc.w = fmaxf(acc.w, 0.f);
    } else {
        // fused L2 row-normalize
        float s = acc.x * acc.x + acc.y * acc.y + acc.z * acc.z + acc.w * acc.w;
        #pragma unroll
        for (int off = 16; off; off >>= 1) s += __shfl_xor_sync(~0u, s, off);
        float inv = 1.0f / sqrtf(s);
        acc.x *= inv; acc.y *= inv; acc.z *= inv; acc.w *= inv;
        *(float4*)(g_A + (size_t)node * 128 + lane * 4) = acc;
    }
    __half2 o01 = __floats2half2_rn(acc.x, acc.y);
    __half2 o23 = __floats2half2_rn(acc.z, acc.w);
    uint2 w;
    w.x = *reinterpret_cast<uint32_t*>(&o01);
    w.y = *reinterpret_cast<uint32_t*>(&o23);
    *(uint2*)(o + (size_t)node * 128 + lane * 4) = w;
}

__global__ void k_anchors(const int* __restrict__ prot) {
    int p = blockIdx.x, t = threadIdx.x;   // 128 threads
    int src = prot[p];
    g_anchors[p * HD + t] = g_A[(size_t)src * HD + t];
    if (t < 64) {
        float a = g_A[(size_t)src * HD + 2 * t];
        float b = g_A[(size_t)src * HD + 2 * t + 1];
        uint32_t h, l;
        hsplit2(a, b, h, l);
        g_AncHi[p * 64 + t] = h;
        g_AncLo[p * 64 + t] = l;
    }
}

__global__ void k_proto_hp(const float* __restrict__ lw1, const float* __restrict__ lb1) {
    __shared__ float a[HD];
    int p = blockIdx.x, j = threadIdx.x;
    a[j] = g_anchors[p * HD + j];
    __syncthreads();
    float acc = lb1[j];
    #pragma unroll 8
    for (int k = 0; k < HD; k++) acc += a[k] * lw1[k * HD + j];
    g_hp[p * HD + j] = fmaxf(acc, 0.f);
}

__global__ void k_proto_out(const float* __restrict__ lw2, const float* __restrict__ lb2,
                            float* __restrict__ op)
{
    __shared__ float h[HD];
    __shared__ float lg[CC];
    __shared__ float red[2];
    int p = blockIdx.x, t = threadIdx.x;   // 64 threads
    h[t] = g_hp[p * HD + t];
    h[t + 64] = g_hp[p * HD + 64 + t];
    __syncthreads();
    if (t < CC) {
        float acc = lb2[t];
        #pragma unroll 8
        for (int j = 0; j < HD; j++) acc += h[j] * lw2[j * CC + t];
        lg[t] = acc;
    }
    __syncthreads();
    if (t == 0) {
        float m = -1e30f;
        for (int c = 0; c < CC; c++) m = fmaxf(m, lg[c]);
        float s = 0.f;
        for (int c = 0; c < CC; c++) s += expf(lg[c] - m);
        red[0] = m; red[1] = logf(s);
    }
    __syncthreads();
    if (t < CC) op[p * CC + t] = lg[t] - red[0] - red[1];
}

__global__ void k_out(const float* __restrict__ xrel, const float* __restrict__ proto,
                      float* __restrict__ out)
{
    __shared__ float sp[PP * CC];
    __shared__ float srow[8][PP];
    int tid = threadIdx.x;
    for (int i = tid; i < PP * CC; i += 256) sp[i] = proto[i];
    int warp = tid >> 5, lane = tid & 31;
    int node = blockIdx.x * 8 + warp;
    if (node < NN) {
        float4 v = *(const float4*)(xrel + (size_t)node * PP + lane * 4);
        *(float4*)&srow[warp][lane * 4] = v;
    }
    __syncthreads();
    if (node >= NN) return;

    const float* r = srow[warp];
    int c2 = 32 + (lane & 7);
    float a0 = 0.f, a1 = 0.f;
    #pragma unroll 8
    for (int p = 0; p < PP; p++) {
        float x = r[p];
        a0 += x * sp[p * CC + lane];
        a1 += x * sp[p * CC + c2];
    }
    float m = a0;
    if (lane < 8) m = fmaxf(m, a1);
    #pragma unroll
    for (int off = 16; off; off >>= 1) m = fmaxf(m, __shfl_xor_sync(~0u, m, off));
    float se = expf(a0 - m) + ((lane < 8) ? expf(a1 - m) : 0.f);
    #pragma unroll
    for (int off = 16; off; off >>= 1) se += __shfl_xor_sync(~0u, se, off);
    float lse = m + logf(se);
    out[(size_t)node * CC + lane] = a0 - lse;
    if (lane < 8) out[(size_t)node * CC + 32 + lane] = a1 - lse;
}

// ---------------------------------------------------------------------------
// launch
// ---------------------------------------------------------------------------
extern "C" void kernel_launch(void* const* d_in, const int* in_sizes, int n_in,
                              void* d_out, int out_size)
{
    const float* x    = (const float*)d_in[0];
    const int*   ei   = (const int*)  d_in[1];
    const int*   prot = (const int*)  d_in[2];
    const float* W0   = (const float*)d_in[3];
    const float* b0   = (const float*)d_in[4];
    const float* Wh   = (const float*)d_in[5];
    const float* bh   = (const float*)d_in[6];
    const float* lw1  = (const float*)d_in[7];
    const float* lb1  = (const float*)d_in[8];
    const float* lw2  = (const float*)d_in[9];
    const float* lb2  = (const float*)d_in[10];

    float* out   = (float*)d_out;                      // [N, C]
    float* xrel  = out + (size_t)NN * CC;              // [N, P]
    float* oprot = xrel + (size_t)NN * PP;             // [P, C]

    __half *pH, *pH2;
    uint32_t *pW0h, *pW0l, *pW1h, *pW1l, *pW2h, *pW2l, *pAnH, *pAnL;
    cudaGetSymbolAddress((void**)&pH, g_H);
    cudaGetSymbolAddress((void**)&pH2, g_H2);
    cudaGetSymbolAddress((void**)&pW0h, g_W0hi);
    cudaGetSymbolAddress((void**)&pW0l, g_W0lo);
    cudaGetSymbolAddress((void**)&pW1h, g_W1hi);
    cudaGetSymbolAddress((void**)&pW1l, g_W1lo);
    cudaGetSymbolAddress((void**)&pW2h, g_W2hi);
    cudaGetSymbolAddress((void**)&pW2l, g_W2lo);
    cudaGetSymbolAddress((void**)&pAnH, g_AncHi);
    cudaGetSymbolAddress((void**)&pAnL, g_AncLo);

    cudaFuncSetAttribute(k_hgemm<0, true, 0>,
                         cudaFuncAttributeMaxDynamicSharedMemorySize, HG_SMEM);
    cudaFuncSetAttribute(k_hgemm<1, true, 0>,
                         cudaFuncAttributeMaxDynamicSharedMemorySize, HG_SMEM);
    cudaFuncSetAttribute(k_hgemm<1, false, 1>,
                         cudaFuncAttributeMaxDynamicSharedMemorySize, HG_SMEM);

    const int TB = 256;
    dim3 gN((NN + TB - 1) / TB);
    dim3 gE((EE + TB - 1) / TB);
    dim3 gGemm((NN + 127) / 128);
    dim3 gWarp8((NN + 7) / 8);

    // --- preprocessing (weights first; independent of graph) ---
    k_convW<<<128, 128>>>(W0, pW0h, pW0l, 128);
    k_convW<<<64, 128>>>(Wh, pW1h, pW1l, 64);
    k_convW<<<64, 128>>>(Wh + HD * HD, pW2h, pW2l, 64);
    k_zero_deg<<<gN, TB>>>();
    k_deg<<<gE, TB>>>(ei);

    // --- layer 0 GEMM: h = x @ W0 (fp16 wire) ---
    k_hgemm<0, true, 0><<<gGemm, 256, HG_SMEM>>>(x, nullptr, pW0h, pW0l,
                                                 nullptr, pH, NN, FIN);

    // --- rest of graph preprocessing ---
    k_dinvrow<<<gN, TB>>>();
    k_fill<<<gE, TB>>>(ei);

    // --- layer 0 aggregate -> relu -> fp16 wire ---
    k_agg<0><<<gWarp8, 256>>>(pH, pH2, b0);

    // --- layer 1 ---
    k_hgemm<1, true, 0><<<gGemm, 256, HG_SMEM>>>(nullptr, pH2, pW1h, pW1l,
                                                 nullptr, pH, NN, HD);
    k_agg<0><<<gWarp8, 256>>>(pH, pH2, bh);

    // --- layer 2 (agg fused with L2 rownorm) ---
    k_hgemm<1, true, 0><<<gGemm, 256, HG_SMEM>>>(nullptr, pH2, pW2h, pW2l,
                                                 nullptr, pH, NN, HD);
    k_agg<1><<<gWarp8, 256>>>(pH, pH2, bh + HD);

    // --- anchors (fp32 + fp16 pairs), proto head ---
    k_anchors<<<PP, HD>>>(prot);
    k_proto_hp<<<PP, HD>>>(lw1, lb1);
    k_proto_out<<<PP, 64>>>(lw2, lb2, oprot);

    // --- x_rel = (hn @ anchors^T + 1) * 0.5 ---
    k_hgemm<1, false, 1><<<gGemm, 256, HG_SMEM>>>(nullptr, pH2, pAnH, pAnL,
                                                  xrel, nullptr, NN, HD);

    // --- out = log_softmax(x_rel @ out_proto) ---
    k_out<<<gWarp8, 256>>>(xrel, oprot, out);
}